// round 2
// baseline (speedup 1.0000x reference)
#include <cuda_runtime.h>

#define EDIM 100
#define NDIM 50
#define TDIM 8
#define CDIM 4
#define UDIM 100
#define LDIM 1000
#define NPAIR 4950
#define KPAD  4960   // pad K to multiple of KT
#define KT    16
#define NP    128    // padded N (E=100 -> 128)
#define TM    64     // batch rows per block in heavy kernel
#define MAXB  8192

// ---------------- device scratch (no allocations allowed) ----------------
__device__ float g_W7f[KPAD * NP];   // folded, transposed W7: [p][e] = W7[e][p] * vv(p)
__device__ int2  g_pairs[KPAD];      // (i,j) for each upper-tri pair p (i-major)
__device__ float g_h5[MAXB * EDIM];
__device__ float g_h6[MAXB * EDIM];

// ---------------- kernel 0a: pair table ----------------
__global__ void k_pairs() {
    int p = blockIdx.x * blockDim.x + threadIdx.x;
    if (p >= KPAD) return;
    int i = 0, j = 0;
    if (p < NPAIR) {
        int rem = p;
        while (rem >= EDIM - 1 - i) { rem -= EDIM - 1 - i; i++; }
        j = i + 1 + rem;
    }
    g_pairs[p] = make_int2(i, j);
}

// ---------------- kernel 0b: fold vv into W7, transpose + pad ----------------
__global__ void k_w7f(const float* __restrict__ v, const float* __restrict__ W7) {
    int idx = blockIdx.x * blockDim.x + threadIdx.x;
    if (idx >= KPAD * NP) return;
    int p = idx / NP, c = idx % NP;
    float val = 0.f;
    if (p < NPAIR && c < EDIM) {
        int2 ij = g_pairs[p];
        float vv = 0.f;
        #pragma unroll
        for (int cc = 0; cc < CDIM; cc++)
            vv += v[ij.x * CDIM + cc] * v[ij.y * CDIM + cc];
        val = W7[c * NPAIR + p] * vv;
    }
    g_W7f[idx] = val;
}

// ---------------- kernel 1: attention pools + h5 + h6 (one block per batch) --
__global__ void k_attn(const float* __restrict__ x,
                       const float* __restrict__ W1, const float* __restrict__ b1,
                       const float* __restrict__ W2,
                       const float* __restrict__ W3, const float* __restrict__ b3,
                       const float* __restrict__ W4,
                       const float* __restrict__ W5, const float* __restrict__ b5,
                       const float* __restrict__ W6, const float* __restrict__ b6) {
    __shared__ float xs[NDIM * 101];      // padded stride 101: conflict-free both axes
    __shared__ float us[2][EDIM];         // folded W2*W1 / W4*W3
    __shared__ float zs[2 * NDIM];
    __shared__ float ws[2 * NDIM];
    __shared__ float qs[2 * EDIM];
    __shared__ float h5s[EDIM];
    __shared__ float red[4];

    int tid = threadIdx.x;
    int b   = blockIdx.x;
    const float* xb = x + (size_t)b * NDIM * EDIM;

    // load x tile (float4, rows padded to 101 in smem)
    for (int li = tid; li < (NDIM * EDIM) / 4; li += blockDim.x) {
        float4 v4 = reinterpret_cast<const float4*>(xb)[li];
        int base = li * 4, n = base / EDIM, e = base % EDIM;  // EDIM%4==0 -> same row
        float* dst = &xs[n * 101 + e];
        dst[0] = v4.x; dst[1] = v4.y; dst[2] = v4.z; dst[3] = v4.w;
    }
    // fold the (linear!) attention MLP: u[e] = sum_t Wb[t]*Wa[t][e]
    if (tid < EDIM) {
        float u0 = 0.f, u1 = 0.f;
        #pragma unroll
        for (int t = 0; t < TDIM; t++) {
            u0 += W2[t] * W1[t * EDIM + tid];
            u1 += W4[t] * W3[t * EDIM + tid];
        }
        us[0][tid] = u0; us[1][tid] = u1;
    }
    __syncthreads();

    // z[n] = exp( x[n]·u + sum_t Wb[t]*ba[t] )
    if (tid < 2 * NDIM) {
        int pool = tid / NDIM, n = tid % NDIM;
        const float* ba = pool ? b3 : b1;
        const float* Wb = pool ? W4 : W2;
        float y = 0.f;
        #pragma unroll
        for (int t = 0; t < TDIM; t++) y += Wb[t] * ba[t];
        const float* xr = &xs[n * 101];
        const float* ur = us[pool];
        for (int e = 0; e < EDIM; e++) y += xr[e] * ur[e];
        zs[tid] = expf(y);
    }
    __syncthreads();

    // softmax over N (z already exp'd per reference)
    if (tid == 0 || tid == 64) {
        int pool = tid >> 6;
        float m = -1e30f;
        for (int n = 0; n < NDIM; n++) m = fmaxf(m, zs[pool * NDIM + n]);
        float s = 0.f;
        for (int n = 0; n < NDIM; n++) s += expf(zs[pool * NDIM + n] - m);
        red[pool * 2] = m; red[pool * 2 + 1] = s;
    }
    __syncthreads();
    if (tid < 2 * NDIM) {
        int pool = tid / NDIM;
        ws[tid] = expf(zs[tid] - red[pool * 2]) / red[pool * 2 + 1];
    }
    __syncthreads();

    // pooled q1/q2
    if (tid < EDIM) {
        float q1 = 0.f, q2 = 0.f;
        for (int n = 0; n < NDIM; n++) {
            float xv = xs[n * 101 + tid];
            q1 += ws[n] * xv;
            q2 += ws[NDIM + n] * xv;
        }
        qs[tid] = q1; qs[EDIM + tid] = q2;
    }
    __syncthreads();

    // h5 = W5 @ cat(q1,q2) + b5 : warp-cooperative rows (coalesced W5 reads)
    int warp = tid >> 5, lane = tid & 31;
    for (int e = warp; e < EDIM; e += 4) {
        const float* w = W5 + e * 2 * EDIM;
        float part = 0.f;
        for (int k = lane; k < 2 * EDIM; k += 32) part += w[k] * qs[k];
        #pragma unroll
        for (int off = 16; off; off >>= 1) part += __shfl_down_sync(0xffffffffu, part, off);
        if (lane == 0) {
            float val = part + b5[e];
            h5s[e] = val;
            g_h5[(size_t)b * EDIM + e] = val;
        }
    }
    __syncthreads();
    // h6 = W6 @ h5 + b6
    for (int e = warp; e < EDIM; e += 4) {
        const float* w = W6 + e * EDIM;
        float part = 0.f;
        for (int k = lane; k < EDIM; k += 32) part += w[k] * h5s[k];
        #pragma unroll
        for (int off = 16; off; off >>= 1) part += __shfl_down_sync(0xffffffffu, part, off);
        if (lane == 0) g_h6[(size_t)b * EDIM + e] = part + b6[e];
    }
}

// ---------------- kernel 2: heavy fused GEMM chain ----------------
// per block: 64 batch rows. cf generated on the fly from h5 tile (never hits HBM).
// h7 = cf @ W7f (K=4960 padded, N=128 padded), then h8 = [h6,h7]@W8^T+b8,
// then out = h8 @ LE, all in shared memory.
#define SH_H5  0        // 64*101 = 6464  (later reused for LE tile: 100*64)
#define SH_CF  6464     // 16*64  = 1024  (cf stored [p][r] for float4 row loads)
#define SH_W7  7488     // 16*128 = 2048
#define SH_H7  9536     // 64*101 = 6464
#define SH_H6  16000    // 64*101 = 6464
#define SH_H8  22464    // 100*64 = 6400  (transposed [u][r])
#define SMEM_FLOATS 28864
#define SMEM_BYTES  (SMEM_FLOATS * 4)

__global__ void __launch_bounds__(256) k_heavy(const float* __restrict__ b7,
                                               const float* __restrict__ W8,
                                               const float* __restrict__ b8,
                                               const float* __restrict__ LE,
                                               float* __restrict__ out, int B) {
    extern __shared__ float sm[];
    float* h5s = sm + SH_H5;
    float* cfs = sm + SH_CF;
    float* w7s = sm + SH_W7;
    float* h7s = sm + SH_H7;
    float* h6s = sm + SH_H6;
    float* h8s = sm + SH_H8;
    float* les = sm + SH_H5;   // alias: h5 dead after K-loop

    int tid = threadIdx.x;
    int b0  = blockIdx.x * TM;

    for (int li = tid; li < TM * EDIM; li += 256) {
        int r = li / EDIM, e = li % EDIM;
        int b = b0 + r;
        h5s[r * 101 + e] = (b < B) ? g_h5[(size_t)b * EDIM + e] : 0.f;
    }

    int tr = tid >> 4, tc = tid & 15;
    int r0 = tr * 4, c0 = tc * 8;      // thread tile: 4 rows x 8 cols (of 64x128)
    float acc[4][8];
    #pragma unroll
    for (int i = 0; i < 4; i++)
        #pragma unroll
        for (int j = 0; j < 8; j++) acc[i][j] = 0.f;
    __syncthreads();

    for (int ko = 0; ko < KPAD / KT; ko++) {
        // stage cf chunk [KT][64]
        #pragma unroll
        for (int q = 0; q < 4; q++) {
            int li = q * 256 + tid;
            int p = li >> 6, r = li & 63;
            int2 ij = g_pairs[ko * KT + p];
            cfs[p * 64 + r] = h5s[r * 101 + ij.x] * h5s[r * 101 + ij.y];
        }
        // stage W7f chunk [KT][128]
        #pragma unroll
        for (int q = 0; q < 2; q++) {
            int li = q * 256 + tid;
            reinterpret_cast<float4*>(w7s)[li] =
                reinterpret_cast<const float4*>(g_W7f)[ko * (KT * NP / 4) + li];
        }
        __syncthreads();
        #pragma unroll
        for (int p = 0; p < KT; p++) {
            float4 cv = *reinterpret_cast<float4*>(&cfs[p * 64 + r0]);
            float4 wa = *reinterpret_cast<float4*>(&w7s[p * NP + c0]);
            float4 wb = *reinterpret_cast<float4*>(&w7s[p * NP + c0 + 4]);
            float cr[4] = {cv.x, cv.y, cv.z, cv.w};
            float wc[8] = {wa.x, wa.y, wa.z, wa.w, wb.x, wb.y, wb.z, wb.w};
            #pragma unroll
            for (int i = 0; i < 4; i++)
                #pragma unroll
                for (int j = 0; j < 8; j++)
                    acc[i][j] += cr[i] * wc[j];
        }
        __syncthreads();
    }

    // h7 tile -> shared (add b7), drop padded cols
    #pragma unroll
    for (int i = 0; i < 4; i++)
        #pragma unroll
        for (int j = 0; j < 8; j++) {
            int c = c0 + j;
            if (c < EDIM) h7s[(r0 + i) * 101 + c] = acc[i][j] + b7[c];
        }
    // h6 tile
    for (int li = tid; li < TM * EDIM; li += 256) {
        int r = li / EDIM, e = li % EDIM;
        int b = b0 + r;
        h6s[r * 101 + e] = (b < B) ? g_h6[(size_t)b * EDIM + e] : 0.f;
    }
    __syncthreads();

    // h8[u][r] = b8[u] + sum_e W8[u][e]*h6 + W8[u][100+e]*h7  (stored transposed)
    for (int li = tid; li < UDIM * TM; li += 256) {
        int u = li / TM, r = li % TM;
        const float* w = W8 + u * 2 * EDIM;
        float a = b8[u];
        for (int e = 0; e < EDIM; e++)
            a += w[e] * h6s[r * 101 + e] + w[EDIM + e] * h7s[r * 101 + e];
        h8s[u * TM + r] = a;
    }
    __syncthreads();

    // out = h8 @ LE, chunks of 64 label cols
    int l0 = tc * 4;
    for (int lt = 0; lt < 16; lt++) {
        for (int li = tid; li < UDIM * 64; li += 256) {
            int u = li / 64, lc = li & 63;
            int l = lt * 64 + lc;
            les[u * 64 + lc] = (l < LDIM) ? LE[u * LDIM + l] : 0.f;
        }
        __syncthreads();
        float a2[4][4] = {};
        for (int u = 0; u < UDIM; u++) {
            float4 hv = *reinterpret_cast<float4*>(&h8s[u * 64 + r0]);
            float4 lv = *reinterpret_cast<float4*>(&les[u * 64 + l0]);
            float hr[4] = {hv.x, hv.y, hv.z, hv.w};
            float lc4[4] = {lv.x, lv.y, lv.z, lv.w};
            #pragma unroll
            for (int i = 0; i < 4; i++)
                #pragma unroll
                for (int j = 0; j < 4; j++)
                    a2[i][j] += hr[i] * lc4[j];
        }
        int lg = lt * 64 + l0;
        if (lg < LDIM) {    // LDIM%4==0 -> whole float4 valid when lg<LDIM
            #pragma unroll
            for (int i = 0; i < 4; i++) {
                int b = b0 + r0 + i;
                if (b < B)
                    *reinterpret_cast<float4*>(&out[(size_t)b * LDIM + lg]) =
                        make_float4(a2[i][0], a2[i][1], a2[i][2], a2[i][3]);
            }
        }
        __syncthreads();
    }
}

// ---------------- launch ----------------
extern "C" void kernel_launch(void* const* d_in, const int* in_sizes, int n_in,
                              void* d_out, int out_size) {
    const float* x  = (const float*)d_in[0];
    const float* v  = (const float*)d_in[1];
    const float* W1 = (const float*)d_in[2];
    const float* b1 = (const float*)d_in[3];
    const float* W2 = (const float*)d_in[4];
    const float* W3 = (const float*)d_in[5];
    const float* b3 = (const float*)d_in[6];
    const float* W4 = (const float*)d_in[7];
    const float* W5 = (const float*)d_in[8];
    const float* b5 = (const float*)d_in[9];
    const float* W6 = (const float*)d_in[10];
    const float* b6 = (const float*)d_in[11];
    const float* W7 = (const float*)d_in[12];
    const float* b7 = (const float*)d_in[13];
    const float* W8 = (const float*)d_in[14];
    const float* b8 = (const float*)d_in[15];
    const float* LE = (const float*)d_in[16];
    float* out = (float*)d_out;

    int B = in_sizes[0] / (NDIM * EDIM);

    k_pairs<<<(KPAD + 255) / 256, 256>>>();
    k_w7f<<<(KPAD * NP + 255) / 256, 256>>>(v, W7);
    k_attn<<<B, 128>>>(x, W1, b1, W2, W3, b3, W4, W5, b5, W6, b6);

    cudaFuncSetAttribute(k_heavy, cudaFuncAttributeMaxDynamicSharedMemorySize, SMEM_BYTES);
    int nblk = (B + TM - 1) / TM;
    k_heavy<<<nblk, 256, SMEM_BYTES>>>(b7, W8, b8, LE, out, B);
}

// round 4
// speedup vs baseline: 1.0717x; 1.0717x over previous
#include <cuda_runtime.h>

#define EDIM 100
#define NDIM 50
#define TDIM 8
#define CDIM 4
#define UDIM 100
#define LDIM 1000
#define NPAIR 4950
#define KPAD  4960
#define KT    16
#define NP    128
#define TM    64
#define MAXB  8192

// ---------------- device scratch ----------------
__device__ float g_W7f[KPAD * NP];   // folded W7: [p][e] = W7[e][p] * vv(p), padded
__device__ int2  g_pairs[KPAD];
__device__ float g_h5[MAXB * EDIM];
__device__ float g_h6[MAXB * EDIM];
__device__ float g_u[2 * EDIM];      // folded attention vectors
__device__ float g_z0[2];            // folded attention biases
__device__ float g_W5t[2 * EDIM * EDIM];  // W5 transposed: [k][e]
__device__ float g_W6t[EDIM * EDIM];      // W6 transposed: [k][e]

// ---------------- kernel: pair table ----------------
__global__ void k_pairs() {
    int p = blockIdx.x * blockDim.x + threadIdx.x;
    if (p >= KPAD) return;
    int i = 0, j = 0;
    if (p < NPAIR) {
        int rem = p;
        while (rem >= EDIM - 1 - i) { rem -= EDIM - 1 - i; i++; }
        j = i + 1 + rem;
    }
    g_pairs[p] = make_int2(i, j);
}

// ---------------- kernel: fold vv into W7 ----------------
__global__ void k_w7f(const float* __restrict__ v, const float* __restrict__ W7) {
    int idx = blockIdx.x * blockDim.x + threadIdx.x;
    if (idx >= KPAD * NP) return;
    int p = idx / NP, c = idx % NP;
    float val = 0.f;
    if (p < NPAIR && c < EDIM) {
        int2 ij = g_pairs[p];
        float vv = 0.f;
        #pragma unroll
        for (int cc = 0; cc < CDIM; cc++)
            vv += v[ij.x * CDIM + cc] * v[ij.y * CDIM + cc];
        val = W7[c * NPAIR + p] * vv;
    }
    g_W7f[idx] = val;
}

// ---------------- kernel: fold attn MLP + transpose W5/W6 ----------------
__global__ void k_prep(const float* __restrict__ W1, const float* __restrict__ b1,
                       const float* __restrict__ W2,
                       const float* __restrict__ W3, const float* __restrict__ b3,
                       const float* __restrict__ W4,
                       const float* __restrict__ W5, const float* __restrict__ W6) {
    int idx = blockIdx.x * blockDim.x + threadIdx.x;
    if (idx < 2 * EDIM * EDIM) {                         // W5t
        int k = idx / EDIM, e = idx % EDIM;
        g_W5t[idx] = W5[e * 2 * EDIM + k];
    } else if (idx < 3 * EDIM * EDIM) {                  // W6t
        int j = idx - 2 * EDIM * EDIM;
        int k = j / EDIM, e = j % EDIM;
        g_W6t[j] = W6[e * EDIM + k];
    } else if (idx < 3 * EDIM * EDIM + 2 * EDIM) {       // u vectors
        int j = idx - 3 * EDIM * EDIM;
        int pool = j / EDIM, e = j % EDIM;
        const float* Wa = pool ? W3 : W1;
        const float* Wb = pool ? W4 : W2;
        float u = 0.f;
        #pragma unroll
        for (int t = 0; t < TDIM; t++) u += Wb[t] * Wa[t * EDIM + e];
        g_u[j] = u;
    } else if (idx < 3 * EDIM * EDIM + 2 * EDIM + 2) {   // z0 scalars
        int pool = idx - (3 * EDIM * EDIM + 2 * EDIM);
        const float* ba = pool ? b3 : b1;
        const float* Wb = pool ? W4 : W2;
        float z = 0.f;
        #pragma unroll
        for (int t = 0; t < TDIM; t++) z += Wb[t] * ba[t];
        g_z0[pool] = z;
    }
}

// ---------------- kernel: attention pools + h5 + h6 (2 batches/block) ------
__global__ void __launch_bounds__(256) k_attn2(const float* __restrict__ x,
                                               const float* __restrict__ b5,
                                               const float* __restrict__ b6, int B) {
    __shared__ float xs[2][NDIM * 101];   // 2 * 5050
    __shared__ float zs[2][2][64];        // exp(logits), then softmax weights
    __shared__ float qs[2][2 * EDIM];
    __shared__ float h5s[2][EDIM];

    int tid = threadIdx.x;
    int half = tid >> 7, ht = tid & 127;
    int b = blockIdx.x * 2 + half;
    bool bv = (b < B);
    const float* xb = x + (size_t)b * NDIM * EDIM;

    // load x tile (float4 reads, scalar stores into stride-101 rows)
    for (int li = ht; li < (NDIM * EDIM) / 4; li += 128) {
        float4 v4 = bv ? reinterpret_cast<const float4*>(xb)[li]
                       : make_float4(0.f, 0.f, 0.f, 0.f);
        int base = li * 4, n = base / EDIM, e = base % EDIM;
        float* dst = &xs[half][n * 101 + e];
        dst[0] = v4.x; dst[1] = v4.y; dst[2] = v4.z; dst[3] = v4.w;
    }
    __syncthreads();

    // z[n] = exp(x[n]·u + z0)
    if (ht < 2 * NDIM) {
        int pool = ht / NDIM, n = ht % NDIM;
        float y = g_z0[pool];
        const float* xr = &xs[half][n * 101];
        const float* ur = &g_u[pool * EDIM];
        #pragma unroll 4
        for (int e = 0; e < EDIM; e++) y += xr[e] * ur[e];
        zs[half][pool][n] = expf(y);
    }
    __syncthreads();

    // softmax over N: one warp per (half,pool)
    {
        int ww = tid >> 5, lane = tid & 31;
        if (ww < 4) {
            int h2 = ww >> 1, pool = ww & 1;
            float z1 = zs[h2][pool][lane];
            float z2 = (lane < NDIM - 32) ? zs[h2][pool][32 + lane] : -1e30f;
            float m = fmaxf(z1, z2);
            #pragma unroll
            for (int off = 16; off; off >>= 1)
                m = fmaxf(m, __shfl_xor_sync(0xffffffffu, m, off));
            float e1 = expf(z1 - m);
            float e2 = (lane < NDIM - 32) ? expf(z2 - m) : 0.f;
            float s = e1 + e2;
            #pragma unroll
            for (int off = 16; off; off >>= 1)
                s += __shfl_xor_sync(0xffffffffu, s, off);
            zs[h2][pool][lane] = e1 / s;
            if (lane < NDIM - 32) zs[h2][pool][32 + lane] = e2 / s;
        }
    }
    __syncthreads();

    // pooled q
    if (ht < EDIM) {
        float q0 = 0.f, q1 = 0.f;
        const float* xr = &xs[half][ht];
        #pragma unroll 2
        for (int n = 0; n < NDIM; n++) {
            float xv = xr[n * 101];
            q0 += zs[half][0][n] * xv;
            q1 += zs[half][1][n] * xv;
        }
        qs[half][ht] = q0; qs[half][EDIM + ht] = q1;
    }
    __syncthreads();

    // h5[e] = b5[e] + sum_k W5t[k][e]*q[k]   (coalesced W5t reads)
    if (ht < EDIM) {
        float a = b5[ht];
        #pragma unroll 4
        for (int k = 0; k < 2 * EDIM; k++)
            a += g_W5t[k * EDIM + ht] * qs[half][k];
        h5s[half][ht] = a;
        if (bv) g_h5[(size_t)b * EDIM + ht] = a;
    }
    __syncthreads();

    // h6
    if (ht < EDIM) {
        float a = b6[ht];
        #pragma unroll 4
        for (int k = 0; k < EDIM; k++)
            a += g_W6t[k * EDIM + ht] * h5s[half][k];
        if (bv) g_h6[(size_t)b * EDIM + ht] = a;
    }
}

// ---------------- heavy fused GEMM chain (512 threads, double-buffered) ----
// smem byte layout:
//   prs  : int2[4960]                         [0, 39680)
//   float base = 39680/4:
//   h5s  : 64*101 = 6464  (aliased by les 100*64 later)
//   cfs  : 2*16*64 = 2048
//   w7s  : 2*16*128 = 4096
//   h7s  : 6464
//   h6s  : 6464
//   h8s  : 100*64 = 6400
#define FB      (39680 / 4)
#define SH_H5   (FB + 0)
#define SH_CF   (FB + 6464)
#define SH_W7   (FB + 8512)
#define SH_H7   (FB + 12608)
#define SH_H6   (FB + 19072)
#define SH_H8   (FB + 25536)
#define SMEM_BYTES (39680 + 31936 * 4)

__global__ void __launch_bounds__(512) k_heavy(const float* __restrict__ b7,
                                               const float* __restrict__ W8,
                                               const float* __restrict__ b8,
                                               const float* __restrict__ LE,
                                               float* __restrict__ out, int B) {
    extern __shared__ float sm[];
    int2*  prs = reinterpret_cast<int2*>(sm);
    float* h5s = sm + SH_H5;
    float* cfs = sm + SH_CF;
    float* w7s = sm + SH_W7;
    float* h7s = sm + SH_H7;
    float* h6s = sm + SH_H6;
    float* h8s = sm + SH_H8;
    float* les = sm + SH_H5;   // alias: h5s dead after K loop

    int tid = threadIdx.x;
    int b0  = blockIdx.x * TM;

    for (int li = tid; li < KPAD; li += 512) prs[li] = g_pairs[li];
    for (int li = tid; li < TM * EDIM; li += 512) {
        int r = li / EDIM, e = li % EDIM;
        int b = b0 + r;
        h5s[r * 101 + e] = (b < B) ? g_h5[(size_t)b * EDIM + e] : 0.f;
    }
    __syncthreads();

    int tr = tid >> 4, tc = tid & 15;
    int r0 = tr * 2, c0 = tc * 8;
    float acc[2][8];
    #pragma unroll
    for (int i = 0; i < 2; i++)
        #pragma unroll
        for (int j = 0; j < 8; j++) acc[i][j] = 0.f;

    // stage chunk ko into buffer parity (ko&1)
    auto stage = [&](int ko) {
        int s = ko & 1;
        #pragma unroll
        for (int q = 0; q < 2; q++) {
            int li = q * 512 + tid;
            int p = li >> 6, r = li & 63;
            int2 ij = prs[ko * KT + p];
            cfs[s * (KT * 64) + p * 64 + r] = h5s[r * 101 + ij.x] * h5s[r * 101 + ij.y];
        }
        reinterpret_cast<float4*>(w7s + s * (KT * NP))[tid] =
            reinterpret_cast<const float4*>(g_W7f)[ko * (KT * NP / 4) + tid];
    };

    stage(0);
    __syncthreads();
    const int NKO = KPAD / KT;
    for (int ko = 0; ko < NKO; ko++) {
        if (ko + 1 < NKO) stage(ko + 1);
        int s = ko & 1;
        const float* cb = cfs + s * (KT * 64);
        const float* wb = w7s + s * (KT * NP);
        #pragma unroll
        for (int p = 0; p < KT; p++) {
            float2 cv = *reinterpret_cast<const float2*>(&cb[p * 64 + r0]);
            float4 wa = *reinterpret_cast<const float4*>(&wb[p * NP + c0]);
            float4 wbb = *reinterpret_cast<const float4*>(&wb[p * NP + c0 + 4]);
            float cr[2] = {cv.x, cv.y};
            float wc[8] = {wa.x, wa.y, wa.z, wa.w, wbb.x, wbb.y, wbb.z, wbb.w};
            #pragma unroll
            for (int i = 0; i < 2; i++)
                #pragma unroll
                for (int j = 0; j < 8; j++)
                    acc[i][j] += cr[i] * wc[j];
        }
        __syncthreads();
    }

    // h7 tile (drop padded cols, add b7)
    #pragma unroll
    for (int i = 0; i < 2; i++)
        #pragma unroll
        for (int j = 0; j < 8; j++) {
            int c = c0 + j;
            if (c < EDIM) h7s[(r0 + i) * 101 + c] = acc[i][j] + b7[c];
        }
    for (int li = tid; li < TM * EDIM; li += 512) {
        int r = li / EDIM, e = li % EDIM;
        int b = b0 + r;
        h6s[r * 101 + e] = (b < B) ? g_h6[(size_t)b * EDIM + e] : 0.f;
    }
    __syncthreads();

    // h8[u][r] (transposed)
    for (int li = tid; li < UDIM * TM; li += 512) {
        int u = li >> 6, r = li & 63;
        const float* w = W8 + u * 2 * EDIM;
        float a = b8[u];
        #pragma unroll 4
        for (int e = 0; e < EDIM; e++)
            a += w[e] * h6s[r * 101 + e] + w[EDIM + e] * h7s[r * 101 + e];
        h8s[u * TM + r] = a;
    }
    __syncthreads();

    // out = h8 @ LE, 64-label chunks
    int l0 = tc * 4;
    for (int lt = 0; lt < 16; lt++) {
        for (int li = tid; li < UDIM * 64; li += 512) {
            int u = li >> 6, lc = li & 63;
            int l = lt * 64 + lc;
            les[u * 64 + lc] = (l < LDIM) ? LE[u * LDIM + l] : 0.f;
        }
        __syncthreads();
        float a2[2][4] = {};
        #pragma unroll 4
        for (int u = 0; u < UDIM; u++) {
            float2 h2 = *reinterpret_cast<const float2*>(&h8s[u * 64 + r0]);
            float4 lv = *reinterpret_cast<const float4*>(&les[u * 64 + l0]);
            float hr[2] = {h2.x, h2.y};
            float lc4[4] = {lv.x, lv.y, lv.z, lv.w};
            #pragma unroll
            for (int i = 0; i < 2; i++)
                #pragma unroll
                for (int j = 0; j < 4; j++)
                    a2[i][j] += hr[i] * lc4[j];
        }
        int lg = lt * 64 + l0;
        if (lg + 3 < LDIM) {
            #pragma unroll
            for (int i = 0; i < 2; i++) {
                int b = b0 + r0 + i;
                if (b < B)
                    *reinterpret_cast<float4*>(&out[(size_t)b * LDIM + lg]) =
                        make_float4(a2[i][0], a2[i][1], a2[i][2], a2[i][3]);
            }
        }
        __syncthreads();
    }
}

// ---------------- launch ----------------
extern "C" void kernel_launch(void* const* d_in, const int* in_sizes, int n_in,
                              void* d_out, int out_size) {
    const float* x  = (const float*)d_in[0];
    const float* v  = (const float*)d_in[1];
    const float* W1 = (const float*)d_in[2];
    const float* b1 = (const float*)d_in[3];
    const float* W2 = (const float*)d_in[4];
    const float* W3 = (const float*)d_in[5];
    const float* b3 = (const float*)d_in[6];
    const float* W4 = (const float*)d_in[7];
    const float* W5 = (const float*)d_in[8];
    const float* b5 = (const float*)d_in[9];
    const float* W6 = (const float*)d_in[10];
    const float* b6 = (const float*)d_in[11];
    const float* W7 = (const float*)d_in[12];
    const float* b7 = (const float*)d_in[13];
    const float* W8 = (const float*)d_in[14];
    const float* b8 = (const float*)d_in[15];
    const float* LE = (const float*)d_in[16];
    float* out = (float*)d_out;

    int B = in_sizes[0] / (NDIM * EDIM);

    k_pairs<<<(KPAD + 255) / 256, 256>>>();
    k_prep<<<(3 * EDIM * EDIM + 2 * EDIM + 2 + 255) / 256, 256>>>(W1, b1, W2, W3, b3, W4, W5, W6);
    k_w7f<<<(KPAD * NP + 255) / 256, 256>>>(v, W7);
    k_attn2<<<(B + 1) / 2, 256>>>(x, b5, b6, B);

    cudaFuncSetAttribute(k_heavy, cudaFuncAttributeMaxDynamicSharedMemorySize, SMEM_BYTES);
    int nblk = (B + TM - 1) / TM;
    k_heavy<<<nblk, 512, SMEM_BYTES>>>(b7, W8, b8, LE, out, B);
}

// round 5
// speedup vs baseline: 2.1309x; 1.9884x over previous
#include <cuda_runtime.h>

#define EDIM 100
#define NDIM 50
#define TDIM 8
#define CDIM 4
#define UDIM 100
#define LDIM 1000
#define NPAIR 4950
#define KPAD  5120           // padded pair-K (multiple of KSPLIT*KT)
#define KT    16
#define NP    128            // padded N for big GEMM
#define TM    64             // batch rows per block
#define KSPLIT 4
#define KSLICE (KPAD / KSPLIT)      // 1280
#define KO_SL  (KSLICE / KT)        // 80
#define MAXB  8192
#define KC    208            // padded 2E for kernel C GEMM1

// ---------------- device scratch ----------------
__device__ float g_W7f[KPAD * NP];        // folded W7: [p][e] = W7[e][p]*vv(p)
__device__ int2  g_pairs[KPAD];
__device__ float g_h5[MAXB * EDIM];
__device__ float g_h6[MAXB * EDIM];
__device__ float g_h7p[KSPLIT * MAXB * NP];   // split-K partials
__device__ float g_u[2 * EDIM];
__device__ float g_z0[2];
__device__ float g_W5t[2 * EDIM * EDIM];  // [k][e]
__device__ float g_W6t[EDIM * EDIM];      // [k][e]
__device__ float g_W8t[KC * 128];         // [k][u] padded (zeros beyond 200x100)

// ---------------- pair table ----------------
__global__ void k_pairs() {
    int p = blockIdx.x * blockDim.x + threadIdx.x;
    if (p >= KPAD) return;
    int i = 0, j = 0;
    if (p < NPAIR) {
        int rem = p;
        while (rem >= EDIM - 1 - i) { rem -= EDIM - 1 - i; i++; }
        j = i + 1 + rem;
    }
    g_pairs[p] = make_int2(i, j);
}

// ---------------- fold vv into W7, transpose (coalesced both sides) --------
__global__ void k_w7f(const float* __restrict__ v, const float* __restrict__ W7) {
    __shared__ float t[32][33];
    int tx = threadIdx.x, ty = threadIdx.y;
    int p0 = blockIdx.x * 32, c0 = blockIdx.y * 32;
    int c = c0 + ty, p = p0 + tx;
    t[ty][tx] = (c < EDIM && p < NPAIR) ? W7[c * NPAIR + p] : 0.f;
    __syncthreads();
    p = p0 + ty; c = c0 + tx;
    if (p < KPAD) {
        float w = t[tx][ty];
        float vv = 0.f;
        if (p < NPAIR) {
            int2 ij = g_pairs[p];
            #pragma unroll
            for (int cc = 0; cc < CDIM; cc++)
                vv += v[ij.x * CDIM + cc] * v[ij.y * CDIM + cc];
        }
        g_W7f[p * NP + c] = w * vv;
    }
}

// ---------------- prep: fold attn MLP, transpose W5/W6/W8 ------------------
__global__ void k_prep(const float* __restrict__ W1, const float* __restrict__ b1,
                       const float* __restrict__ W2,
                       const float* __restrict__ W3, const float* __restrict__ b3,
                       const float* __restrict__ W4,
                       const float* __restrict__ W5, const float* __restrict__ W6,
                       const float* __restrict__ W8) {
    int idx = blockIdx.x * blockDim.x + threadIdx.x;
    const int N1 = 2 * EDIM * EDIM;            // W5t
    const int N2 = N1 + EDIM * EDIM;           // W6t
    const int N3 = N2 + 2 * EDIM;              // u
    const int N4 = N3 + 2;                     // z0
    const int N5 = N4 + KC * 128;              // W8t
    if (idx < N1) {
        int k = idx / EDIM, e = idx % EDIM;
        g_W5t[idx] = W5[e * 2 * EDIM + k];
    } else if (idx < N2) {
        int j = idx - N1;
        int k = j / EDIM, e = j % EDIM;
        g_W6t[j] = W6[e * EDIM + k];
    } else if (idx < N3) {
        int j = idx - N2;
        int pool = j / EDIM, e = j % EDIM;
        const float* Wa = pool ? W3 : W1;
        const float* Wb = pool ? W4 : W2;
        float u = 0.f;
        #pragma unroll
        for (int t = 0; t < TDIM; t++) u += Wb[t] * Wa[t * EDIM + e];
        g_u[j] = u;
    } else if (idx < N4) {
        int pool = idx - N3;
        const float* ba = pool ? b3 : b1;
        const float* Wb = pool ? W4 : W2;
        float z = 0.f;
        #pragma unroll
        for (int t = 0; t < TDIM; t++) z += Wb[t] * ba[t];
        g_z0[pool] = z;
    } else if (idx < N5) {
        int j = idx - N4;
        int k = j >> 7, u = j & 127;
        g_W8t[j] = (k < 2 * EDIM && u < UDIM) ? W8[u * 2 * EDIM + k] : 0.f;
    }
}

// ---------------- attention pools + h5 + h6 (smem-light, 2 batches) --------
__global__ void __launch_bounds__(256) k_attn3(const float* __restrict__ x,
                                               const float* __restrict__ b5,
                                               const float* __restrict__ b6, int B) {
    __shared__ float zs[2][2][64];
    __shared__ float qs[2][2 * EDIM];
    __shared__ float h5s[2][EDIM];

    int tid = threadIdx.x;
    int g = tid >> 7, wg_tid = tid & 127;
    int w = tid >> 5, lane = tid & 31;
    int ww = w & 3;
    int b = blockIdx.x * 2 + g;
    bool bv = (b < B);
    const float* xb = x + (size_t)b * NDIM * EDIM;

    // cache folded attention vectors in registers (per-lane slices)
    float u00 = g_u[lane], u01 = g_u[lane + 32], u02 = g_u[lane + 64];
    float u03 = (lane < 4) ? g_u[lane + 96] : 0.f;
    float u10 = g_u[EDIM + lane], u11 = g_u[EDIM + lane + 32], u12 = g_u[EDIM + lane + 64];
    float u13 = (lane < 4) ? g_u[EDIM + lane + 96] : 0.f;
    float z00 = g_z0[0], z01 = g_z0[1];

    // phase 1: row dots (warp-cooperative, coalesced)
    for (int row = ww; row < NDIM; row += 4) {
        float y0 = 0.f, y1 = 0.f;
        if (bv) {
            const float* xr = xb + row * EDIM;
            float x0 = xr[lane], x1 = xr[lane + 32], x2 = xr[lane + 64];
            float x3 = (lane < 4) ? xr[lane + 96] : 0.f;
            y0 = x0 * u00 + x1 * u01 + x2 * u02 + x3 * u03;
            y1 = x0 * u10 + x1 * u11 + x2 * u12 + x3 * u13;
        }
        #pragma unroll
        for (int off = 16; off; off >>= 1) {
            y0 += __shfl_xor_sync(0xffffffffu, y0, off);
            y1 += __shfl_xor_sync(0xffffffffu, y1, off);
        }
        if (lane == 0) {
            zs[g][0][row] = expf(y0 + z00);
            zs[g][1][row] = expf(y1 + z01);
        }
    }
    __syncthreads();

    // phase 2: softmax over N (exp'd logits, per reference): warps {0,1,4,5}
    if (ww < 2) {
        int pool = ww;
        float z1 = zs[g][pool][lane];
        float z2 = (lane < NDIM - 32) ? zs[g][pool][32 + lane] : -1e30f;
        float m = fmaxf(z1, z2);
        #pragma unroll
        for (int off = 16; off; off >>= 1)
            m = fmaxf(m, __shfl_xor_sync(0xffffffffu, m, off));
        float e1 = expf(z1 - m);
        float e2 = (lane < NDIM - 32) ? expf(z2 - m) : 0.f;
        float s = e1 + e2;
        #pragma unroll
        for (int off = 16; off; off >>= 1)
            s += __shfl_xor_sync(0xffffffffu, s, off);
        zs[g][pool][lane] = e1 / s;
        if (lane < NDIM - 32) zs[g][pool][32 + lane] = e2 / s;
    }
    __syncthreads();

    // phase 3: pooled q (coalesced re-read of x; hits L1/L2)
    if (wg_tid < EDIM) {
        float a0 = 0.f, a1 = 0.f;
        if (bv) {
            #pragma unroll 5
            for (int n = 0; n < NDIM; n++) {
                float xv = xb[n * EDIM + wg_tid];
                a0 += zs[g][0][n] * xv;
                a1 += zs[g][1][n] * xv;
            }
        }
        qs[g][wg_tid] = a0;
        qs[g][EDIM + wg_tid] = a1;
    }
    __syncthreads();

    // phase 4: h5
    if (wg_tid < EDIM) {
        float a = b5[wg_tid];
        #pragma unroll 4
        for (int k = 0; k < 2 * EDIM; k++)
            a += g_W5t[k * EDIM + wg_tid] * qs[g][k];
        h5s[g][wg_tid] = a;
        if (bv) g_h5[(size_t)b * EDIM + wg_tid] = a;
    }
    __syncthreads();

    // phase 5: h6
    if (wg_tid < EDIM) {
        float a = b6[wg_tid];
        #pragma unroll 4
        for (int k = 0; k < EDIM; k++)
            a += g_W6t[k * EDIM + wg_tid] * h5s[g][k];
        if (bv) g_h6[(size_t)b * EDIM + wg_tid] = a;
    }
}

// ---------------- kernel B: split-K big GEMM, 8x8 tiles --------------------
// smem: h5s 64*101=6464 | cfs 2*16*64=2048 | w7s 2*16*128=4096  (50,432 B)
#define B_H5 0
#define B_CF 6464
#define B_W7 8512
#define B_SMEM_BYTES (12608 * 4)

__global__ void __launch_bounds__(128) k_B(int B) {
    extern __shared__ float sm[];
    float* h5s = sm + B_H5;
    float* cfs = sm + B_CF;
    float* w7s = sm + B_W7;

    int tid = threadIdx.x;
    int b0  = blockIdx.x * TM;
    int ks  = blockIdx.y;

    for (int li = tid; li < TM * EDIM; li += 128) {
        int r = li / EDIM, e = li % EDIM;
        int b = b0 + r;
        h5s[r * 101 + e] = (b < B) ? g_h5[(size_t)b * EDIM + e] : 0.f;
    }
    __syncthreads();

    int tr = tid >> 4, tc = tid & 15;
    int r0 = tr * 8, c0 = tc * 8;
    float acc[8][8];
    #pragma unroll
    for (int i = 0; i < 8; i++)
        #pragma unroll
        for (int j = 0; j < 8; j++) acc[i][j] = 0.f;

    auto stage = [&](int ko) {
        int s = ko & 1;
        int kg = ks * KO_SL + ko;
        #pragma unroll
        for (int q = 0; q < 8; q++) {
            int li = q * 128 + tid;
            int p = li >> 6, r = li & 63;
            int2 ij = g_pairs[kg * KT + p];
            cfs[s * (KT * 64) + p * 64 + r] = h5s[r * 101 + ij.x] * h5s[r * 101 + ij.y];
        }
        #pragma unroll
        for (int q = 0; q < 4; q++) {
            int li = q * 128 + tid;
            reinterpret_cast<float4*>(w7s + s * (KT * NP))[li] =
                reinterpret_cast<const float4*>(g_W7f)[kg * (KT * NP / 4) + li];
        }
    };

    stage(0);
    __syncthreads();
    for (int ko = 0; ko < KO_SL; ko++) {
        if (ko + 1 < KO_SL) stage(ko + 1);
        int s = ko & 1;
        const float* cb = cfs + s * (KT * 64);
        const float* wb = w7s + s * (KT * NP);
        #pragma unroll
        for (int p = 0; p < KT; p++) {
            float4 ca = *reinterpret_cast<const float4*>(&cb[p * 64 + r0]);
            float4 cb4 = *reinterpret_cast<const float4*>(&cb[p * 64 + r0 + 4]);
            float4 wa = *reinterpret_cast<const float4*>(&wb[p * NP + c0]);
            float4 wb4 = *reinterpret_cast<const float4*>(&wb[p * NP + c0 + 4]);
            float cr[8] = {ca.x, ca.y, ca.z, ca.w, cb4.x, cb4.y, cb4.z, cb4.w};
            float wc[8] = {wa.x, wa.y, wa.z, wa.w, wb4.x, wb4.y, wb4.z, wb4.w};
            #pragma unroll
            for (int i = 0; i < 8; i++)
                #pragma unroll
                for (int j = 0; j < 8; j++)
                    acc[i][j] += cr[i] * wc[j];
        }
        __syncthreads();
    }

    // store partials (coalesced float4)
    float* dst = g_h7p + ((size_t)ks * MAXB + b0) * NP;
    #pragma unroll
    for (int i = 0; i < 8; i++) {
        *reinterpret_cast<float4*>(&dst[(r0 + i) * NP + c0]) =
            make_float4(acc[i][0], acc[i][1], acc[i][2], acc[i][3]);
        *reinterpret_cast<float4*>(&dst[(r0 + i) * NP + c0 + 4]) =
            make_float4(acc[i][4], acc[i][5], acc[i][6], acc[i][7]);
    }
}

// ---------------- kernel C: combine partials + h8 + label projection -------
// smem floats: h67s [64][208]=13312 | w8ts [208][128]=26624 (aliased by les [100][128]=12800) | h8s [128][64]=8192
#define C_H67 0
#define C_W8  13312
#define C_H8  39936
#define C_LES C_W8
#define C_SMEM_BYTES (48128 * 4)

__global__ void __launch_bounds__(256) k_C(const float* __restrict__ b7,
                                           const float* __restrict__ b8,
                                           const float* __restrict__ LE,
                                           float* __restrict__ out, int B) {
    extern __shared__ float sm[];
    float* h67s = sm + C_H67;
    float* w8ts = sm + C_W8;
    float* h8s  = sm + C_H8;
    float* les  = sm + C_LES;

    int tid = threadIdx.x;
    int b0  = blockIdx.x * TM;

    // stage A = [h6 | h7+b7 | 0pad] : [64][208]
    for (int li = tid; li < TM * KC; li += 256) {
        int r = li / KC, k = li % KC;
        int b = b0 + r;
        float val = 0.f;
        if (b < B) {
            if (k < EDIM) {
                val = g_h6[(size_t)b * EDIM + k];
            } else if (k < 2 * EDIM) {
                int e = k - EDIM;
                float a = b7[e];
                #pragma unroll
                for (int s = 0; s < KSPLIT; s++)
                    a += g_h7p[((size_t)s * MAXB + b) * NP + e];
                val = a;
            }
        }
        h67s[li] = val;
    }
    // stage W8t [208][128]
    for (int li = tid; li < KC * 128 / 4; li += 256)
        reinterpret_cast<float4*>(w8ts)[li] = reinterpret_cast<const float4*>(g_W8t)[li];
    __syncthreads();

    // GEMM1: h8[64][128] = A[64][208] @ W8t[208][128]; store transposed [u][r]
    int tr = tid >> 4, tu = tid & 15;
    int r0 = tr * 4, u0 = tu * 8;
    {
        float acc[4][8];
        #pragma unroll
        for (int i = 0; i < 4; i++)
            #pragma unroll
            for (int j = 0; j < 8; j++) acc[i][j] = 0.f;
        #pragma unroll 8
        for (int k = 0; k < KC; k++) {
            float a0 = h67s[(r0 + 0) * KC + k];
            float a1 = h67s[(r0 + 1) * KC + k];
            float a2 = h67s[(r0 + 2) * KC + k];
            float a3 = h67s[(r0 + 3) * KC + k];
            float4 wa = *reinterpret_cast<const float4*>(&w8ts[k * 128 + u0]);
            float4 wb = *reinterpret_cast<const float4*>(&w8ts[k * 128 + u0 + 4]);
            float wv[8] = {wa.x, wa.y, wa.z, wa.w, wb.x, wb.y, wb.z, wb.w};
            float av[4] = {a0, a1, a2, a3};
            #pragma unroll
            for (int i = 0; i < 4; i++)
                #pragma unroll
                for (int j = 0; j < 8; j++)
                    acc[i][j] += av[i] * wv[j];
        }
        #pragma unroll
        for (int j = 0; j < 8; j++) {
            int u = u0 + j;
            if (u < UDIM) {
                float bb = b8[u];
                #pragma unroll
                for (int i = 0; i < 4; i++)
                    h8s[u * TM + r0 + i] = acc[i][j] + bb;
            }
        }
    }
    __syncthreads();

    // GEMM2: out[64][1000] = h8[64][100] @ LE[100][1000], 128-col tiles
    int tl = tid & 15;
    int l0 = tl * 8;
    for (int lt = 0; lt < 8; lt++) {
        for (int li = tid; li < UDIM * 128; li += 256) {
            int u = li >> 7, lc = li & 127;
            int l = lt * 128 + lc;
            les[u * 128 + lc] = (l < LDIM) ? LE[u * LDIM + l] : 0.f;
        }
        __syncthreads();
        float acc[4][8];
        #pragma unroll
        for (int i = 0; i < 4; i++)
            #pragma unroll
            for (int j = 0; j < 8; j++) acc[i][j] = 0.f;
        #pragma unroll 4
        for (int u = 0; u < UDIM; u++) {
            float4 hv = *reinterpret_cast<const float4*>(&h8s[u * TM + r0]);
            float4 la = *reinterpret_cast<const float4*>(&les[u * 128 + l0]);
            float4 lb = *reinterpret_cast<const float4*>(&les[u * 128 + l0 + 4]);
            float hr[4] = {hv.x, hv.y, hv.z, hv.w};
            float lv[8] = {la.x, la.y, la.z, la.w, lb.x, lb.y, lb.z, lb.w};
            #pragma unroll
            for (int i = 0; i < 4; i++)
                #pragma unroll
                for (int j = 0; j < 8; j++)
                    acc[i][j] += hr[i] * lv[j];
        }
        int lg = lt * 128 + l0;
        if (lg < LDIM) {   // lg multiple of 8; valid chunks end at 999
            #pragma unroll
            for (int i = 0; i < 4; i++) {
                int b = b0 + r0 + i;
                if (b < B) {
                    *reinterpret_cast<float4*>(&out[(size_t)b * LDIM + lg]) =
                        make_float4(acc[i][0], acc[i][1], acc[i][2], acc[i][3]);
                    *reinterpret_cast<float4*>(&out[(size_t)b * LDIM + lg + 4]) =
                        make_float4(acc[i][4], acc[i][5], acc[i][6], acc[i][7]);
                }
            }
        }
        __syncthreads();
    }
}

// ---------------- launch ----------------
extern "C" void kernel_launch(void* const* d_in, const int* in_sizes, int n_in,
                              void* d_out, int out_size) {
    const float* x  = (const float*)d_in[0];
    const float* v  = (const float*)d_in[1];
    const float* W1 = (const float*)d_in[2];
    const float* b1 = (const float*)d_in[3];
    const float* W2 = (const float*)d_in[4];
    const float* W3 = (const float*)d_in[5];
    const float* b3 = (const float*)d_in[6];
    const float* W4 = (const float*)d_in[7];
    const float* W5 = (const float*)d_in[8];
    const float* b5 = (const float*)d_in[9];
    const float* W6 = (const float*)d_in[10];
    const float* b6 = (const float*)d_in[11];
    const float* W7 = (const float*)d_in[12];
    const float* b7 = (const float*)d_in[13];
    const float* W8 = (const float*)d_in[14];
    const float* b8 = (const float*)d_in[15];
    const float* LE = (const float*)d_in[16];
    float* out = (float*)d_out;

    int B = in_sizes[0] / (NDIM * EDIM);
    int nMB = (B + TM - 1) / TM;

    k_pairs<<<(KPAD + 255) / 256, 256>>>();
    {
        dim3 tg(32, 32), bg((KPAD + 31) / 32, (NP + 31) / 32);
        k_w7f<<<bg, tg>>>(v, W7);
    }
    k_prep<<<(3 * EDIM * EDIM + 2 * EDIM + 2 + KC * 128 + 255) / 256, 256>>>(
        W1, b1, W2, W3, b3, W4, W5, W6, W8);
    k_attn3<<<(B + 1) / 2, 256>>>(x, b5, b6, B);

    cudaFuncSetAttribute(k_B, cudaFuncAttributeMaxDynamicSharedMemorySize, B_SMEM_BYTES);
    dim3 bgrid(nMB, KSPLIT);
    k_B<<<bgrid, 128, B_SMEM_BYTES>>>(B);

    cudaFuncSetAttribute(k_C, cudaFuncAttributeMaxDynamicSharedMemorySize, C_SMEM_BYTES);
    k_C<<<nMB, 256, C_SMEM_BYTES>>>(b7, b8, LE, out, B);
}

// round 7
// speedup vs baseline: 2.8539x; 1.3393x over previous
#include <cuda_runtime.h>
#include <cuda_bf16.h>
#include <cstdint>

#define EDIM 100
#define NDIM 50
#define TDIM 8
#define CDIM 4
#define UDIM 100
#define LDIM 1000
#define NPAIR 4950
#define KPAD  5120
#define NP    128
#define KSPLIT 2
#define KSLICE (KPAD / KSPLIT)        // 2560
#define NKSTEP (KPAD / 16)            // 320 ksteps total
#define NKS_SL (KSLICE / 16)          // 160 per slice
#define NCHUNK (NKS_SL / 4)           // 40 chunks (64 k each)
#define MAXB  8192
#define TMC   64
#define KC    208

// ---------------- device scratch ----------------
__device__ __align__(16) int2  g_pairs[KPAD];
__device__ float g_h5[MAXB * EDIM];
__device__ float g_h6[MAXB * EDIM];
__device__ float g_h7p[KSPLIT * MAXB * NP];
__device__ float g_u[2 * EDIM];
__device__ float g_z0[2];
__device__ float g_W5t[2 * EDIM * EDIM];
__device__ float g_W6t[EDIM * EDIM];
__device__ float g_W8t[KC * 128];
// B fragments in exact mma.sync per-lane layout: [kstep][ntile(16)][lane(32)] uint2
__device__ __align__(16) uint2 g_Bfh[NKSTEP * 16 * 32];
__device__ __align__(16) uint2 g_Bfl[NKSTEP * 16 * 32];

// ---------------- helpers ----------------
__device__ __forceinline__ void mma16816(float* d, const uint32_t* a, uint2 b) {
    asm volatile(
        "mma.sync.aligned.m16n8k16.row.col.f32.bf16.bf16.f32 "
        "{%0,%1,%2,%3}, {%4,%5,%6,%7}, {%8,%9}, {%0,%1,%2,%3};"
        : "+f"(d[0]), "+f"(d[1]), "+f"(d[2]), "+f"(d[3])
        : "r"(a[0]), "r"(a[1]), "r"(a[2]), "r"(a[3]), "r"(b.x), "r"(b.y));
}
__device__ __forceinline__ void mkfrag(const float* rw, int2 p0, int2 p1,
                                       uint32_t& hi, uint32_t& lo) {
    float v0 = rw[p0.x] * rw[p0.y];
    float v1 = rw[p1.x] * rw[p1.y];
    __nv_bfloat16 h0 = __float2bfloat16(v0), h1 = __float2bfloat16(v1);
    __nv_bfloat16 l0 = __float2bfloat16(v0 - __bfloat162float(h0));
    __nv_bfloat16 l1 = __float2bfloat16(v1 - __bfloat162float(h1));
    hi = (uint32_t)__bfloat16_as_ushort(h0) | ((uint32_t)__bfloat16_as_ushort(h1) << 16);
    lo = (uint32_t)__bfloat16_as_ushort(l0) | ((uint32_t)__bfloat16_as_ushort(l1) << 16);
}

// ---------------- pair table ----------------
__global__ void k_pairs() {
    int p = blockIdx.x * blockDim.x + threadIdx.x;
    if (p >= KPAD) return;
    int i = 0, j = 0;
    if (p < NPAIR) {
        int rem = p;
        while (rem >= EDIM - 1 - i) { rem -= EDIM - 1 - i; i++; }
        j = i + 1 + rem;
    }
    g_pairs[p] = make_int2(i, j);
}

// ---------------- build B fragments (folded W7*vv, hi/lo split) ------------
__global__ void k_bfrag(const float* __restrict__ v, const float* __restrict__ W7) {
    int idx = blockIdx.x * blockDim.x + threadIdx.x;
    if (idx >= NKSTEP * 512) return;
    int ks = idx >> 9, rem = idx & 511;
    int nt = rem >> 5, l = rem & 31;
    int n = nt * 8 + (l >> 2);
    int c0 = (l & 3) * 2;
    uint32_t hreg[2], lreg[2];
    #pragma unroll
    for (int r = 0; r < 2; r++) {
        uint32_t hp = 0, lp = 0;
        #pragma unroll
        for (int h = 0; h < 2; h++) {
            int k = ks * 16 + r * 8 + c0 + h;
            float w = 0.f;
            if (k < NPAIR && n < EDIM) {
                int2 ij = g_pairs[k];
                float vv = 0.f;
                #pragma unroll
                for (int cc = 0; cc < CDIM; cc++)
                    vv += v[ij.x * CDIM + cc] * v[ij.y * CDIM + cc];
                w = W7[n * NPAIR + k] * vv;
            }
            __nv_bfloat16 hi = __float2bfloat16(w);
            __nv_bfloat16 lo = __float2bfloat16(w - __bfloat162float(hi));
            hp |= (uint32_t)__bfloat16_as_ushort(hi) << (h * 16);
            lp |= (uint32_t)__bfloat16_as_ushort(lo) << (h * 16);
        }
        hreg[r] = hp; lreg[r] = lp;
    }
    g_Bfh[idx] = make_uint2(hreg[0], hreg[1]);
    g_Bfl[idx] = make_uint2(lreg[0], lreg[1]);
}

// ---------------- prep: fold attn MLP, transpose W5/W6/W8 ------------------
__global__ void k_prep(const float* __restrict__ W1, const float* __restrict__ b1,
                       const float* __restrict__ W2,
                       const float* __restrict__ W3, const float* __restrict__ b3,
                       const float* __restrict__ W4,
                       const float* __restrict__ W5, const float* __restrict__ W6,
                       const float* __restrict__ W8) {
    int idx = blockIdx.x * blockDim.x + threadIdx.x;
    const int N1 = 2 * EDIM * EDIM;
    const int N2 = N1 + EDIM * EDIM;
    const int N3 = N2 + 2 * EDIM;
    const int N4 = N3 + 2;
    const int N5 = N4 + KC * 128;
    if (idx < N1) {
        int k = idx / EDIM, e = idx % EDIM;
        g_W5t[idx] = W5[e * 2 * EDIM + k];
    } else if (idx < N2) {
        int j = idx - N1;
        int k = j / EDIM, e = j % EDIM;
        g_W6t[j] = W6[e * EDIM + k];
    } else if (idx < N3) {
        int j = idx - N2;
        int pool = j / EDIM, e = j % EDIM;
        const float* Wa = pool ? W3 : W1;
        const float* Wb = pool ? W4 : W2;
        float u = 0.f;
        #pragma unroll
        for (int t = 0; t < TDIM; t++) u += Wb[t] * Wa[t * EDIM + e];
        g_u[j] = u;
    } else if (idx < N4) {
        int pool = idx - N3;
        const float* ba = pool ? b3 : b1;
        const float* Wb = pool ? W4 : W2;
        float z = 0.f;
        #pragma unroll
        for (int t = 0; t < TDIM; t++) z += Wb[t] * ba[t];
        g_z0[pool] = z;
    } else if (idx < N5) {
        int j = idx - N4;
        int k = j >> 7, u = j & 127;
        g_W8t[j] = (k < 2 * EDIM && u < UDIM) ? W8[u * 2 * EDIM + k] : 0.f;
    }
}

// ---------------- attention pools + h5 + h6 --------------------------------
__global__ void __launch_bounds__(256) k_attn3(const float* __restrict__ x,
                                               const float* __restrict__ b5,
                                               const float* __restrict__ b6, int B) {
    __shared__ float zs[2][2][64];
    __shared__ float qs[2][2 * EDIM];
    __shared__ float h5s[2][EDIM];

    int tid = threadIdx.x;
    int g = tid >> 7, wg_tid = tid & 127;
    int w = tid >> 5, lane = tid & 31;
    int ww = w & 3;
    int b = blockIdx.x * 2 + g;
    bool bv = (b < B);
    const float* xb = x + (size_t)b * NDIM * EDIM;

    float u00 = g_u[lane], u01 = g_u[lane + 32], u02 = g_u[lane + 64];
    float u03 = (lane < 4) ? g_u[lane + 96] : 0.f;
    float u10 = g_u[EDIM + lane], u11 = g_u[EDIM + lane + 32], u12 = g_u[EDIM + lane + 64];
    float u13 = (lane < 4) ? g_u[EDIM + lane + 96] : 0.f;
    float z00 = g_z0[0], z01 = g_z0[1];

    for (int row = ww; row < NDIM; row += 4) {
        float y0 = 0.f, y1 = 0.f;
        if (bv) {
            const float* xr = xb + row * EDIM;
            float x0 = xr[lane], x1 = xr[lane + 32], x2 = xr[lane + 64];
            float x3 = (lane < 4) ? xr[lane + 96] : 0.f;
            y0 = x0 * u00 + x1 * u01 + x2 * u02 + x3 * u03;
            y1 = x0 * u10 + x1 * u11 + x2 * u12 + x3 * u13;
        }
        #pragma unroll
        for (int off = 16; off; off >>= 1) {
            y0 += __shfl_xor_sync(0xffffffffu, y0, off);
            y1 += __shfl_xor_sync(0xffffffffu, y1, off);
        }
        if (lane == 0) {
            zs[g][0][row] = expf(y0 + z00);
            zs[g][1][row] = expf(y1 + z01);
        }
    }
    __syncthreads();

    if (ww < 2) {
        int pool = ww;
        float z1 = zs[g][pool][lane];
        float z2 = (lane < NDIM - 32) ? zs[g][pool][32 + lane] : -1e30f;
        float m = fmaxf(z1, z2);
        #pragma unroll
        for (int off = 16; off; off >>= 1)
            m = fmaxf(m, __shfl_xor_sync(0xffffffffu, m, off));
        float e1 = expf(z1 - m);
        float e2 = (lane < NDIM - 32) ? expf(z2 - m) : 0.f;
        float s = e1 + e2;
        #pragma unroll
        for (int off = 16; off; off >>= 1)
            s += __shfl_xor_sync(0xffffffffu, s, off);
        zs[g][pool][lane] = e1 / s;
        if (lane < NDIM - 32) zs[g][pool][32 + lane] = e2 / s;
    }
    __syncthreads();

    if (wg_tid < EDIM) {
        float a0 = 0.f, a1 = 0.f;
        if (bv) {
            #pragma unroll 5
            for (int n = 0; n < NDIM; n++) {
                float xv = xb[n * EDIM + wg_tid];
                a0 += zs[g][0][n] * xv;
                a1 += zs[g][1][n] * xv;
            }
        }
        qs[g][wg_tid] = a0;
        qs[g][EDIM + wg_tid] = a1;
    }
    __syncthreads();

    if (wg_tid < EDIM) {
        float a = b5[wg_tid];
        #pragma unroll 4
        for (int k = 0; k < 2 * EDIM; k++)
            a += g_W5t[k * EDIM + wg_tid] * qs[g][k];
        h5s[g][wg_tid] = a;
        if (bv) g_h5[(size_t)b * EDIM + wg_tid] = a;
    }
    __syncthreads();

    if (wg_tid < EDIM) {
        float a = b6[wg_tid];
        #pragma unroll 4
        for (int k = 0; k < EDIM; k++)
            a += g_W6t[k * EDIM + wg_tid] * h5s[g][k];
        if (bv) g_h6[(size_t)b * EDIM + wg_tid] = a;
    }
}

// ---------------- kernel B: split-bf16 mma.sync GEMM -----------------------
// smem bytes:
//   h5s   : [128][101] f32 = 51712
//   pairs : int2[2560]      = 20480        @51712
//   sBh   : 2 x 16384                       @72192
//   sBl   : 2 x 16384                       @104960
#define SB_H5 0
#define SB_PR 51712
#define SB_BH 72192
#define SB_BL 104960
#define SB_SMEM 137728

__global__ void __launch_bounds__(256, 1) k_B(int B) {
    extern __shared__ __align__(16) char smem[];
    float* h5s = (float*)(smem + SB_H5);
    int2*  ps  = (int2*)(smem + SB_PR);

    int tid = threadIdx.x;
    int lane = tid & 31, warp = tid >> 5;
    int wm = warp >> 1, wn = warp & 1;
    int b0 = blockIdx.x * 128;
    int ks = blockIdx.y;

    // stage h5 tile
    for (int li = tid; li < 128 * EDIM; li += 256) {
        int r = li / EDIM, e = li % EDIM;
        int b = b0 + r;
        h5s[r * 101 + e] = (b < B) ? g_h5[(size_t)b * EDIM + e] : 0.f;
    }
    // stage slice pair table
    {
        const int4* src = (const int4*)(g_pairs + ks * KSLICE);
        int4* dst = (int4*)ps;
        #pragma unroll
        for (int q = 0; q < 5; q++) dst[tid + q * 256] = src[tid + q * 256];
    }

    float acc[2][8][4];
    #pragma unroll
    for (int mi = 0; mi < 2; mi++)
        #pragma unroll
        for (int nt = 0; nt < 8; nt++)
            #pragma unroll
            for (int q = 0; q < 4; q++) acc[mi][nt][q] = 0.f;

    auto stageB = [&](int ch) {
        int s = ch & 1;
        size_t goff = ((size_t)ks * NKS_SL + ch * 4) * 512;  // uint2 units
        const float4* srcH = (const float4*)(g_Bfh + goff);
        const float4* srcL = (const float4*)(g_Bfl + goff);
        float4* dH = (float4*)(smem + SB_BH + s * 16384);
        float4* dL = (float4*)(smem + SB_BL + s * 16384);
        #pragma unroll
        for (int q = 0; q < 4; q++) {
            dH[tid + q * 256] = srcH[tid + q * 256];
            dL[tid + q * 256] = srcL[tid + q * 256];
        }
    };

    stageB(0);
    __syncthreads();

    int c0 = (lane & 3) * 2;
    for (int ch = 0; ch < NCHUNK; ch++) {
        if (ch + 1 < NCHUNK) stageB(ch + 1);
        int s = ch & 1;
        const uint2* bhB = (const uint2*)(smem + SB_BH + s * 16384);
        const uint2* blB = (const uint2*)(smem + SB_BL + s * 16384);
        #pragma unroll
        for (int kl = 0; kl < 4; kl++) {
            int kb = (ch * 4 + kl) * 16;
            int2 pA0 = ps[kb + c0], pA1 = ps[kb + c0 + 1];
            int2 pB0 = ps[kb + c0 + 8], pB1 = ps[kb + c0 + 9];
            uint32_t ahi[2][4], alo[2][4];
            #pragma unroll
            for (int mi = 0; mi < 2; mi++) {
                const float* ra = &h5s[(wm * 32 + mi * 16 + (lane >> 2)) * 101];
                const float* rb = ra + 8 * 101;
                mkfrag(ra, pA0, pA1, ahi[mi][0], alo[mi][0]);
                mkfrag(rb, pA0, pA1, ahi[mi][1], alo[mi][1]);
                mkfrag(ra, pB0, pB1, ahi[mi][2], alo[mi][2]);
                mkfrag(rb, pB0, pB1, ahi[mi][3], alo[mi][3]);
            }
            const uint2* bh = bhB + kl * 512 + lane;
            const uint2* bl = blB + kl * 512 + lane;
            #pragma unroll
            for (int nt = 0; nt < 8; nt++) {
                uint2 Bh = bh[(wn * 8 + nt) * 32];
                uint2 Bl = bl[(wn * 8 + nt) * 32];
                #pragma unroll
                for (int mi = 0; mi < 2; mi++) {
                    mma16816(acc[mi][nt], ahi[mi], Bh);
                    mma16816(acc[mi][nt], ahi[mi], Bl);
                    mma16816(acc[mi][nt], alo[mi], Bh);
                }
            }
        }
        __syncthreads();
    }

    // epilogue: write partials
    float* base = g_h7p + (size_t)ks * MAXB * NP;
    #pragma unroll
    for (int mi = 0; mi < 2; mi++) {
        int row = wm * 32 + mi * 16 + (lane >> 2);
        int bA = b0 + row, bB = bA + 8;
        #pragma unroll
        for (int nt = 0; nt < 8; nt++) {
            int col = wn * 64 + nt * 8 + (lane & 3) * 2;
            if (bA < B)
                *(float2*)&base[(size_t)bA * NP + col] =
                    make_float2(acc[mi][nt][0], acc[mi][nt][1]);
            if (bB < B)
                *(float2*)&base[(size_t)bB * NP + col] =
                    make_float2(acc[mi][nt][2], acc[mi][nt][3]);
        }
    }
}

// ---------------- kernel C: combine + h8 + label projection ----------------
#define C_H67 0
#define C_W8  13312
#define C_H8  39936
#define C_LES C_W8
#define C_SMEM_BYTES (48128 * 4)

__global__ void __launch_bounds__(256) k_C(const float* __restrict__ b7,
                                           const float* __restrict__ b8,
                                           const float* __restrict__ LE,
                                           float* __restrict__ out, int B) {
    extern __shared__ float sm[];
    float* h67s = sm + C_H67;
    float* w8ts = sm + C_W8;
    float* h8s  = sm + C_H8;
    float* les  = sm + C_LES;

    int tid = threadIdx.x;
    int b0  = blockIdx.x * TMC;

    for (int li = tid; li < TMC * KC; li += 256) {
        int r = li / KC, k = li % KC;
        int b = b0 + r;
        float val = 0.f;
        if (b < B) {
            if (k < EDIM) {
                val = g_h6[(size_t)b * EDIM + k];
            } else if (k < 2 * EDIM) {
                int e = k - EDIM;
                float a = b7[e];
                #pragma unroll
                for (int s = 0; s < KSPLIT; s++)
                    a += g_h7p[((size_t)s * MAXB + b) * NP + e];
                val = a;
            }
        }
        h67s[li] = val;
    }
    for (int li = tid; li < KC * 128 / 4; li += 256)
        reinterpret_cast<float4*>(w8ts)[li] = reinterpret_cast<const float4*>(g_W8t)[li];
    __syncthreads();

    int tr = tid >> 4, tu = tid & 15;
    int r0 = tr * 4, u0 = tu * 8;
    {
        float acc[4][8];
        #pragma unroll
        for (int i = 0; i < 4; i++)
            #pragma unroll
            for (int j = 0; j < 8; j++) acc[i][j] = 0.f;
        #pragma unroll 8
        for (int k = 0; k < KC; k++) {
            float a0 = h67s[(r0 + 0) * KC + k];
            float a1 = h67s[(r0 + 1) * KC + k];
            float a2 = h67s[(r0 + 2) * KC + k];
            float a3 = h67s[(r0 + 3) * KC + k];
            float4 wa = *reinterpret_cast<const float4*>(&w8ts[k * 128 + u0]);
            float4 wb = *reinterpret_cast<const float4*>(&w8ts[k * 128 + u0 + 4]);
            float wv[8] = {wa.x, wa.y, wa.z, wa.w, wb.x, wb.y, wb.z, wb.w};
            float av[4] = {a0, a1, a2, a3};
            #pragma unroll
            for (int i = 0; i < 4; i++)
                #pragma unroll
                for (int j = 0; j < 8; j++)
                    acc[i][j] += av[i] * wv[j];
        }
        #pragma unroll
        for (int j = 0; j < 8; j++) {
            int u = u0 + j;
            if (u < UDIM) {
                float bb = b8[u];
                #pragma unroll
                for (int i = 0; i < 4; i++)
                    h8s[u * TMC + r0 + i] = acc[i][j] + bb;
            }
        }
    }
    __syncthreads();

    int tl = tid & 15;
    int l0 = tl * 8;
    for (int lt = 0; lt < 8; lt++) {
        for (int li = tid; li < UDIM * 128; li += 256) {
            int u = li >> 7, lc = li & 127;
            int l = lt * 128 + lc;
            les[u * 128 + lc] = (l < LDIM) ? LE[u * LDIM + l] : 0.f;
        }
        __syncthreads();
        float acc[4][8];
        #pragma unroll
        for (int i = 0; i < 4; i++)
            #pragma unroll
            for (int j = 0; j < 8; j++) acc[i][j] = 0.f;
        #pragma unroll 4
        for (int u = 0; u < UDIM; u++) {
            float4 hv = *reinterpret_cast<const float4*>(&h8s[u * TMC + r0]);
            float4 la = *reinterpret_cast<const float4*>(&les[u * 128 + l0]);
            float4 lb = *reinterpret_cast<const float4*>(&les[u * 128 + l0 + 4]);
            float hr[4] = {hv.x, hv.y, hv.z, hv.w};
            float lv[8] = {la.x, la.y, la.z, la.w, lb.x, lb.y, lb.z, lb.w};
            #pragma unroll
            for (int i = 0; i < 4; i++)
                #pragma unroll
                for (int j = 0; j < 8; j++)
                    acc[i][j] += hr[i] * lv[j];
        }
        int lg = lt * 128 + l0;
        if (lg < LDIM) {
            #pragma unroll
            for (int i = 0; i < 4; i++) {
                int b = b0 + r0 + i;
                if (b < B) {
                    *reinterpret_cast<float4*>(&out[(size_t)b * LDIM + lg]) =
                        make_float4(acc[i][0], acc[i][1], acc[i][2], acc[i][3]);
                    *reinterpret_cast<float4*>(&out[(size_t)b * LDIM + lg + 4]) =
                        make_float4(acc[i][4], acc[i][5], acc[i][6], acc[i][7]);
                }
            }
        }
        __syncthreads();
    }
}

// ---------------- launch ----------------
extern "C" void kernel_launch(void* const* d_in, const int* in_sizes, int n_in,
                              void* d_out, int out_size) {
    const float* x  = (const float*)d_in[0];
    const float* v  = (const float*)d_in[1];
    const float* W1 = (const float*)d_in[2];
    const float* b1 = (const float*)d_in[3];
    const float* W2 = (const float*)d_in[4];
    const float* W3 = (const float*)d_in[5];
    const float* b3 = (const float*)d_in[6];
    const float* W4 = (const float*)d_in[7];
    const float* W5 = (const float*)d_in[8];
    const float* b5 = (const float*)d_in[9];
    const float* W6 = (const float*)d_in[10];
    const float* b6 = (const float*)d_in[11];
    const float* W7 = (const float*)d_in[12];
    const float* b7 = (const float*)d_in[13];
    const float* W8 = (const float*)d_in[14];
    const float* b8 = (const float*)d_in[15];
    const float* LE = (const float*)d_in[16];
    float* out = (float*)d_out;

    int B = in_sizes[0] / (NDIM * EDIM);

    k_pairs<<<(KPAD + 255) / 256, 256>>>();
    k_bfrag<<<(NKSTEP * 512 + 255) / 256, 256>>>(v, W7);
    k_prep<<<(3 * EDIM * EDIM + 2 * EDIM + 2 + KC * 128 + 255) / 256, 256>>>(
        W1, b1, W2, W3, b3, W4, W5, W6, W8);
    k_attn3<<<(B + 1) / 2, 256>>>(x, b5, b6, B);

    cudaFuncSetAttribute(k_B, cudaFuncAttributeMaxDynamicSharedMemorySize, SB_SMEM);
    dim3 bgrid((B + 127) / 128, KSPLIT);
    k_B<<<bgrid, 256, SB_SMEM>>>(B);

    cudaFuncSetAttribute(k_C, cudaFuncAttributeMaxDynamicSharedMemorySize, C_SMEM_BYTES);
    k_C<<<(B + TMC - 1) / TMC, 256, C_SMEM_BYTES>>>(b7, b8, LE, out, B);
}

// round 8
// speedup vs baseline: 2.8794x; 1.0089x over previous
#include <cuda_runtime.h>
#include <cuda_bf16.h>
#include <cstdint>

#define EDIM 100
#define NDIM 50
#define TDIM 8
#define CDIM 4
#define UDIM 100
#define LDIM 1000
#define NPAIR 4950
#define KPAD  5120
#define NP    128
#define KSPLIT 2
#define KSLICE (KPAD / KSPLIT)        // 2560
#define NKSTEP (KPAD / 16)            // 320
#define NKS_SL (KSLICE / 16)          // 160
#define NCHUNK (NKS_SL / 4)           // 40
#define MAXB  8192
#define TMC   64
#define KC    208
#define NLT   125                     // 1000/8 label n-tiles
#define NKSC  7                       // ceil(100/16) ksteps for label GEMM

// ---------------- device scratch ----------------
__device__ __align__(16) int2  g_pairs[KPAD];
__device__ float g_h5[MAXB * EDIM];
__device__ float g_h6[MAXB * EDIM];
__device__ float g_h7p[KSPLIT * MAXB * NP];
__device__ __align__(16) float g_u[2 * EDIM];
__device__ float g_z0[2];
__device__ float g_W5t[2 * EDIM * EDIM];
__device__ float g_W6t[EDIM * EDIM];
__device__ float g_W8t[KC * 128];
// B fragments, exact mma.sync per-lane layout: [kstep][ntile][lane] uint2
__device__ __align__(16) uint2 g_Bfh[NKSTEP * 16 * 32];
__device__ __align__(16) uint2 g_Bfl[NKSTEP * 16 * 32];
// LE fragments for label GEMM: [kstep(7)][ntile(125)][lane(32)]
__device__ __align__(16) uint2 g_LEfh[NKSC * NLT * 32];
__device__ __align__(16) uint2 g_LEfl[NKSC * NLT * 32];

// ---------------- helpers ----------------
__device__ __forceinline__ void mma16816(float* d, const uint32_t* a, uint2 b) {
    asm volatile(
        "mma.sync.aligned.m16n8k16.row.col.f32.bf16.bf16.f32 "
        "{%0,%1,%2,%3}, {%4,%5,%6,%7}, {%8,%9}, {%0,%1,%2,%3};"
        : "+f"(d[0]), "+f"(d[1]), "+f"(d[2]), "+f"(d[3])
        : "r"(a[0]), "r"(a[1]), "r"(a[2]), "r"(a[3]), "r"(b.x), "r"(b.y));
}
__device__ __forceinline__ void mkfrag(const float* rw, int2 p0, int2 p1,
                                       uint32_t& hi, uint32_t& lo) {
    float v0 = rw[p0.x] * rw[p0.y];
    float v1 = rw[p1.x] * rw[p1.y];
    __nv_bfloat16 h0 = __float2bfloat16(v0), h1 = __float2bfloat16(v1);
    __nv_bfloat16 l0 = __float2bfloat16(v0 - __bfloat162float(h0));
    __nv_bfloat16 l1 = __float2bfloat16(v1 - __bfloat162float(h1));
    hi = (uint32_t)__bfloat16_as_ushort(h0) | ((uint32_t)__bfloat16_as_ushort(h1) << 16);
    lo = (uint32_t)__bfloat16_as_ushort(l0) | ((uint32_t)__bfloat16_as_ushort(l1) << 16);
}
__device__ __forceinline__ void splitpack(float v0, float v1,
                                          uint32_t& hi, uint32_t& lo) {
    __nv_bfloat16 h0 = __float2bfloat16(v0), h1 = __float2bfloat16(v1);
    __nv_bfloat16 l0 = __float2bfloat16(v0 - __bfloat162float(h0));
    __nv_bfloat16 l1 = __float2bfloat16(v1 - __bfloat162float(h1));
    hi = (uint32_t)__bfloat16_as_ushort(h0) | ((uint32_t)__bfloat16_as_ushort(h1) << 16);
    lo = (uint32_t)__bfloat16_as_ushort(l0) | ((uint32_t)__bfloat16_as_ushort(l1) << 16);
}

// ---------------- pair table ----------------
__global__ void k_pairs() {
    int p = blockIdx.x * blockDim.x + threadIdx.x;
    if (p >= KPAD) return;
    int i = 0, j = 0;
    if (p < NPAIR) {
        int rem = p;
        while (rem >= EDIM - 1 - i) { rem -= EDIM - 1 - i; i++; }
        j = i + 1 + rem;
    }
    g_pairs[p] = make_int2(i, j);
}

// ---------------- build W7 B-fragments (folded vv, hi/lo split) ------------
__global__ void k_bfrag(const float* __restrict__ v, const float* __restrict__ W7) {
    int idx = blockIdx.x * blockDim.x + threadIdx.x;
    if (idx >= NKSTEP * 512) return;
    int ks = idx >> 9, rem = idx & 511;
    int nt = rem >> 5, l = rem & 31;
    int n = nt * 8 + (l >> 2);
    int c0 = (l & 3) * 2;
    uint32_t hreg[2], lreg[2];
    #pragma unroll
    for (int r = 0; r < 2; r++) {
        uint32_t hp = 0, lp = 0;
        #pragma unroll
        for (int h = 0; h < 2; h++) {
            int k = ks * 16 + r * 8 + c0 + h;
            float w = 0.f;
            if (k < NPAIR && n < EDIM) {
                int2 ij = g_pairs[k];
                float vv = 0.f;
                #pragma unroll
                for (int cc = 0; cc < CDIM; cc++)
                    vv += v[ij.x * CDIM + cc] * v[ij.y * CDIM + cc];
                w = W7[n * NPAIR + k] * vv;
            }
            __nv_bfloat16 hi = __float2bfloat16(w);
            __nv_bfloat16 lo = __float2bfloat16(w - __bfloat162float(hi));
            hp |= (uint32_t)__bfloat16_as_ushort(hi) << (h * 16);
            lp |= (uint32_t)__bfloat16_as_ushort(lo) << (h * 16);
        }
        hreg[r] = hp; lreg[r] = lp;
    }
    g_Bfh[idx] = make_uint2(hreg[0], hreg[1]);
    g_Bfl[idx] = make_uint2(lreg[0], lreg[1]);
}

// ---------------- build LE B-fragments (hi/lo split) -----------------------
__global__ void k_lef(const float* __restrict__ LE) {
    int idx = blockIdx.x * blockDim.x + threadIdx.x;
    if (idx >= NKSC * NLT * 32) return;
    int ks = idx / (NLT * 32), rem = idx % (NLT * 32);
    int nt = rem >> 5, l = rem & 31;
    int n = nt * 8 + (l >> 2);
    int c0 = (l & 3) * 2;
    uint32_t hreg[2], lreg[2];
    #pragma unroll
    for (int r = 0; r < 2; r++) {
        uint32_t hp = 0, lp = 0;
        #pragma unroll
        for (int h = 0; h < 2; h++) {
            int k = ks * 16 + r * 8 + c0 + h;
            float w = (k < UDIM) ? LE[k * LDIM + n] : 0.f;
            __nv_bfloat16 hi = __float2bfloat16(w);
            __nv_bfloat16 lo = __float2bfloat16(w - __bfloat162float(hi));
            hp |= (uint32_t)__bfloat16_as_ushort(hi) << (h * 16);
            lp |= (uint32_t)__bfloat16_as_ushort(lo) << (h * 16);
        }
        hreg[r] = hp; lreg[r] = lp;
    }
    g_LEfh[idx] = make_uint2(hreg[0], hreg[1]);
    g_LEfl[idx] = make_uint2(lreg[0], lreg[1]);
}

// ---------------- prep: fold attn MLP, transpose W5/W6/W8 ------------------
__global__ void k_prep(const float* __restrict__ W1, const float* __restrict__ b1,
                       const float* __restrict__ W2,
                       const float* __restrict__ W3, const float* __restrict__ b3,
                       const float* __restrict__ W4,
                       const float* __restrict__ W5, const float* __restrict__ W6,
                       const float* __restrict__ W8) {
    int idx = blockIdx.x * blockDim.x + threadIdx.x;
    const int N1 = 2 * EDIM * EDIM;
    const int N2 = N1 + EDIM * EDIM;
    const int N3 = N2 + 2 * EDIM;
    const int N4 = N3 + 2;
    const int N5 = N4 + KC * 128;
    if (idx < N1) {
        int k = idx / EDIM, e = idx % EDIM;
        g_W5t[idx] = W5[e * 2 * EDIM + k];
    } else if (idx < N2) {
        int j = idx - N1;
        int k = j / EDIM, e = j % EDIM;
        g_W6t[j] = W6[e * EDIM + k];
    } else if (idx < N3) {
        int j = idx - N2;
        int pool = j / EDIM, e = j % EDIM;
        const float* Wa = pool ? W3 : W1;
        const float* Wb = pool ? W4 : W2;
        float u = 0.f;
        #pragma unroll
        for (int t = 0; t < TDIM; t++) u += Wb[t] * Wa[t * EDIM + e];
        g_u[j] = u;
    } else if (idx < N4) {
        int pool = idx - N3;
        const float* ba = pool ? b3 : b1;
        const float* Wb = pool ? W4 : W2;
        float z = 0.f;
        #pragma unroll
        for (int t = 0; t < TDIM; t++) z += Wb[t] * ba[t];
        g_z0[pool] = z;
    } else if (idx < N5) {
        int j = idx - N4;
        int k = j >> 7, u = j & 127;
        g_W8t[j] = (k < 2 * EDIM && u < UDIM) ? W8[u * 2 * EDIM + k] : 0.f;
    }
}

// ---------------- attention pools + h5 + h6 (single x pass, float4) --------
__global__ void __launch_bounds__(256) k_attn4(const float* __restrict__ x,
                                               const float* __restrict__ b5,
                                               const float* __restrict__ b6, int B) {
    __shared__ float zs[2][2][64];
    __shared__ float qp[2][4][2][EDIM];   // per-warp column partials
    __shared__ float qs[2][2 * EDIM];
    __shared__ float h5s[2][EDIM];

    int tid = threadIdx.x;
    int g = tid >> 7, wg_tid = tid & 127;
    int lane = tid & 31;
    int w = tid >> 5;
    int ww = w & 3;
    int b = blockIdx.x * 2 + g;
    bool bv = (b < B);
    const float* xb = x + (size_t)b * NDIM * EDIM;

    // u vectors as float4 per lane (cols 4l..4l+3), lanes 25..31 idle
    float4 u0 = make_float4(0.f, 0.f, 0.f, 0.f), u1 = u0;
    if (lane < 25) {
        u0 = *(const float4*)&g_u[4 * lane];
        u1 = *(const float4*)&g_u[EDIM + 4 * lane];
    }
    float z00 = g_z0[0], z01 = g_z0[1];

    // load rows ww, ww+4, ... into registers (float4, single DRAM pass)
    int nrows = (ww < 2) ? 13 : 12;
    float4 xv[13];
    #pragma unroll
    for (int r = 0; r < 13; r++) {
        xv[r] = make_float4(0.f, 0.f, 0.f, 0.f);
        if (r < nrows && bv && lane < 25) {
            int n = ww + r * 4;
            xv[r] = *(const float4*)&xb[n * EDIM + 4 * lane];
        }
    }

    // phase 1: row dots + exp
    #pragma unroll
    for (int r = 0; r < 13; r++) {
        if (r < nrows) {
            float y0 = xv[r].x * u0.x + xv[r].y * u0.y + xv[r].z * u0.z + xv[r].w * u0.w;
            float y1 = xv[r].x * u1.x + xv[r].y * u1.y + xv[r].z * u1.z + xv[r].w * u1.w;
            #pragma unroll
            for (int off = 16; off; off >>= 1) {
                y0 += __shfl_xor_sync(0xffffffffu, y0, off);
                y1 += __shfl_xor_sync(0xffffffffu, y1, off);
            }
            if (lane == 0) {
                int n = ww + r * 4;
                zs[g][0][n] = expf(y0 + z00);
                zs[g][1][n] = expf(y1 + z01);
            }
        }
    }
    __syncthreads();

    // phase 2: softmax over N — warps 0..3 handle (batch, pool)
    if (w < 4) {
        int gg = w >> 1, pool = w & 1;
        float z1 = zs[gg][pool][lane];
        float z2 = (lane < NDIM - 32) ? zs[gg][pool][32 + lane] : -1e30f;
        float m = fmaxf(z1, z2);
        #pragma unroll
        for (int off = 16; off; off >>= 1)
            m = fmaxf(m, __shfl_xor_sync(0xffffffffu, m, off));
        float e1 = expf(z1 - m);
        float e2 = (lane < NDIM - 32) ? expf(z2 - m) : 0.f;
        float s = e1 + e2;
        #pragma unroll
        for (int off = 16; off; off >>= 1)
            s += __shfl_xor_sync(0xffffffffu, s, off);
        zs[gg][pool][lane] = e1 / s;
        if (lane < NDIM - 32) zs[gg][pool][32 + lane] = e2 / s;
    }
    __syncthreads();

    // phase 3: pooled q from registers (no x re-read)
    float4 q0 = make_float4(0.f, 0.f, 0.f, 0.f), q1 = q0;
    #pragma unroll
    for (int r = 0; r < 13; r++) {
        if (r < nrows) {
            int n = ww + r * 4;
            float w0 = zs[g][0][n], w1 = zs[g][1][n];
            q0.x += w0 * xv[r].x; q0.y += w0 * xv[r].y;
            q0.z += w0 * xv[r].z; q0.w += w0 * xv[r].w;
            q1.x += w1 * xv[r].x; q1.y += w1 * xv[r].y;
            q1.z += w1 * xv[r].z; q1.w += w1 * xv[r].w;
        }
    }
    if (lane < 25) {
        *(float4*)&qp[g][ww][0][4 * lane] = q0;
        *(float4*)&qp[g][ww][1][4 * lane] = q1;
    }
    __syncthreads();
    if (wg_tid < EDIM) {
        qs[g][wg_tid] = qp[g][0][0][wg_tid] + qp[g][1][0][wg_tid] +
                        qp[g][2][0][wg_tid] + qp[g][3][0][wg_tid];
        qs[g][EDIM + wg_tid] = qp[g][0][1][wg_tid] + qp[g][1][1][wg_tid] +
                               qp[g][2][1][wg_tid] + qp[g][3][1][wg_tid];
    }
    __syncthreads();

    // phase 4: h5
    if (wg_tid < EDIM) {
        float a = b5[wg_tid];
        #pragma unroll 4
        for (int k = 0; k < 2 * EDIM; k++)
            a += g_W5t[k * EDIM + wg_tid] * qs[g][k];
        h5s[g][wg_tid] = a;
        if (bv) g_h5[(size_t)b * EDIM + wg_tid] = a;
    }
    __syncthreads();

    // phase 5: h6
    if (wg_tid < EDIM) {
        float a = b6[wg_tid];
        #pragma unroll 4
        for (int k = 0; k < EDIM; k++)
            a += g_W6t[k * EDIM + wg_tid] * h5s[g][k];
        if (bv) g_h6[(size_t)b * EDIM + wg_tid] = a;
    }
}

// ---------------- kernel B: split-bf16 mma.sync GEMM -----------------------
#define SB_H5 0
#define SB_PR 51712
#define SB_BH 72192
#define SB_BL 104960
#define SB_SMEM 137728

__global__ void __launch_bounds__(256, 1) k_B(int B) {
    extern __shared__ __align__(16) char smem[];
    float* h5s = (float*)(smem + SB_H5);
    int2*  ps  = (int2*)(smem + SB_PR);

    int tid = threadIdx.x;
    int lane = tid & 31, warp = tid >> 5;
    int wm = warp >> 1, wn = warp & 1;
    int b0 = blockIdx.x * 128;
    int ks = blockIdx.y;

    for (int li = tid; li < 128 * EDIM; li += 256) {
        int r = li / EDIM, e = li % EDIM;
        int b = b0 + r;
        h5s[r * 101 + e] = (b < B) ? g_h5[(size_t)b * EDIM + e] : 0.f;
    }
    {
        const int4* src = (const int4*)(g_pairs + ks * KSLICE);
        int4* dst = (int4*)ps;
        #pragma unroll
        for (int q = 0; q < 5; q++) dst[tid + q * 256] = src[tid + q * 256];
    }

    float acc[2][8][4];
    #pragma unroll
    for (int mi = 0; mi < 2; mi++)
        #pragma unroll
        for (int nt = 0; nt < 8; nt++)
            #pragma unroll
            for (int q = 0; q < 4; q++) acc[mi][nt][q] = 0.f;

    auto stageB = [&](int ch) {
        int s = ch & 1;
        size_t goff = ((size_t)ks * NKS_SL + ch * 4) * 512;
        const float4* srcH = (const float4*)(g_Bfh + goff);
        const float4* srcL = (const float4*)(g_Bfl + goff);
        float4* dH = (float4*)(smem + SB_BH + s * 16384);
        float4* dL = (float4*)(smem + SB_BL + s * 16384);
        #pragma unroll
        for (int q = 0; q < 4; q++) {
            dH[tid + q * 256] = srcH[tid + q * 256];
            dL[tid + q * 256] = srcL[tid + q * 256];
        }
    };

    stageB(0);
    __syncthreads();

    int c0 = (lane & 3) * 2;
    for (int ch = 0; ch < NCHUNK; ch++) {
        if (ch + 1 < NCHUNK) stageB(ch + 1);
        int s = ch & 1;
        const uint2* bhB = (const uint2*)(smem + SB_BH + s * 16384);
        const uint2* blB = (const uint2*)(smem + SB_BL + s * 16384);
        #pragma unroll
        for (int kl = 0; kl < 4; kl++) {
            int kb = (ch * 4 + kl) * 16;
            int2 pA0 = ps[kb + c0], pA1 = ps[kb + c0 + 1];
            int2 pB0 = ps[kb + c0 + 8], pB1 = ps[kb + c0 + 9];
            uint32_t ahi[2][4], alo[2][4];
            #pragma unroll
            for (int mi = 0; mi < 2; mi++) {
                const float* ra = &h5s[(wm * 32 + mi * 16 + (lane >> 2)) * 101];
                const float* rb = ra + 8 * 101;
                mkfrag(ra, pA0, pA1, ahi[mi][0], alo[mi][0]);
                mkfrag(rb, pA0, pA1, ahi[mi][1], alo[mi][1]);
                mkfrag(ra, pB0, pB1, ahi[mi][2], alo[mi][2]);
                mkfrag(rb, pB0, pB1, ahi[mi][3], alo[mi][3]);
            }
            const uint2* bh = bhB + kl * 512 + lane;
            const uint2* bl = blB + kl * 512 + lane;
            #pragma unroll
            for (int nt = 0; nt < 8; nt++) {
                uint2 Bh = bh[(wn * 8 + nt) * 32];
                uint2 Bl = bl[(wn * 8 + nt) * 32];
                #pragma unroll
                for (int mi = 0; mi < 2; mi++) {
                    mma16816(acc[mi][nt], ahi[mi], Bh);
                    mma16816(acc[mi][nt], ahi[mi], Bl);
                    mma16816(acc[mi][nt], alo[mi], Bh);
                }
            }
        }
        __syncthreads();
    }

    float* base = g_h7p + (size_t)ks * MAXB * NP;
    #pragma unroll
    for (int mi = 0; mi < 2; mi++) {
        int row = wm * 32 + mi * 16 + (lane >> 2);
        int bA = b0 + row, bB = bA + 8;
        #pragma unroll
        for (int nt = 0; nt < 8; nt++) {
            int col = wn * 64 + nt * 8 + (lane & 3) * 2;
            if (bA < B)
                *(float2*)&base[(size_t)bA * NP + col] =
                    make_float2(acc[mi][nt][0], acc[mi][nt][1]);
            if (bB < B)
                *(float2*)&base[(size_t)bB * NP + col] =
                    make_float2(acc[mi][nt][2], acc[mi][nt][3]);
        }
    }
}

// ---------------- kernel C: combine + h8 (fp32) + label GEMM (mma) ---------
// smem floats: h67s [64][208] @0 (13312) | w8ts [208][128] @13312 (26624) |
//              h8s  [64][112] @39936 (7168)  -> 47104 floats = 188416 B
#define C_H67 0
#define C_W8  13312
#define C_H8  39936
#define C_SMEM_BYTES (47104 * 4)

__global__ void __launch_bounds__(256) k_C(const float* __restrict__ b7,
                                           const float* __restrict__ b8,
                                           float* __restrict__ out, int B) {
    extern __shared__ float sm[];
    float* h67s = sm + C_H67;
    float* w8ts = sm + C_W8;
    float* h8s  = sm + C_H8;

    int tid = threadIdx.x;
    int b0  = blockIdx.x * TMC;

    for (int li = tid; li < TMC * KC; li += 256) {
        int r = li / KC, k = li % KC;
        int b = b0 + r;
        float val = 0.f;
        if (b < B) {
            if (k < EDIM) {
                val = g_h6[(size_t)b * EDIM + k];
            } else if (k < 2 * EDIM) {
                int e = k - EDIM;
                float a = b7[e];
                #pragma unroll
                for (int s = 0; s < KSPLIT; s++)
                    a += g_h7p[((size_t)s * MAXB + b) * NP + e];
                val = a;
            }
        }
        h67s[li] = val;
    }
    for (int li = tid; li < KC * 128 / 4; li += 256)
        reinterpret_cast<float4*>(w8ts)[li] = reinterpret_cast<const float4*>(g_W8t)[li];
    __syncthreads();

    // GEMM1 (fp32): h8[64][112] = A[64][208] @ W8t[208][128] + b8, zero-padded k
    int tr = tid >> 4, tu = tid & 15;
    int r0 = tr * 4, u0 = tu * 8;
    {
        float acc[4][8];
        #pragma unroll
        for (int i = 0; i < 4; i++)
            #pragma unroll
            for (int j = 0; j < 8; j++) acc[i][j] = 0.f;
        #pragma unroll 8
        for (int k = 0; k < KC; k++) {
            float a0 = h67s[(r0 + 0) * KC + k];
            float a1 = h67s[(r0 + 1) * KC + k];
            float a2 = h67s[(r0 + 2) * KC + k];
            float a3 = h67s[(r0 + 3) * KC + k];
            float4 wa = *reinterpret_cast<const float4*>(&w8ts[k * 128 + u0]);
            float4 wb = *reinterpret_cast<const float4*>(&w8ts[k * 128 + u0 + 4]);
            float wv[8] = {wa.x, wa.y, wa.z, wa.w, wb.x, wb.y, wb.z, wb.w};
            float av[4] = {a0, a1, a2, a3};
            #pragma unroll
            for (int i = 0; i < 4; i++)
                #pragma unroll
                for (int j = 0; j < 8; j++)
                    acc[i][j] += av[i] * wv[j];
        }
        #pragma unroll
        for (int j = 0; j < 8; j++) {
            int u = u0 + j;
            if (u < 112) {
                bool uv = (u < UDIM);
                float bb = uv ? b8[u] : 0.f;
                #pragma unroll
                for (int i = 0; i < 4; i++)
                    h8s[(r0 + i) * 112 + u] = uv ? (acc[i][j] + bb) : 0.f;
            }
        }
    }
    __syncthreads();

    // GEMM2 (split-bf16 mma): out[64][1000] = h8[64][112] @ LE_frag
    {
        int lane = tid & 31, warp = tid >> 5;
        int wm = warp >> 1, wn = warp & 1;
        int ar = wm * 16 + (lane >> 2);
        int ac = (lane & 3) * 2;

        uint32_t ah[NKSC][4], al[NKSC][4];
        #pragma unroll
        for (int ksq = 0; ksq < NKSC; ksq++) {
            float2 v00 = *(const float2*)&h8s[ar * 112 + ksq * 16 + ac];
            float2 v10 = *(const float2*)&h8s[(ar + 8) * 112 + ksq * 16 + ac];
            float2 v01 = *(const float2*)&h8s[ar * 112 + ksq * 16 + ac + 8];
            float2 v11 = *(const float2*)&h8s[(ar + 8) * 112 + ksq * 16 + ac + 8];
            splitpack(v00.x, v00.y, ah[ksq][0], al[ksq][0]);
            splitpack(v10.x, v10.y, ah[ksq][1], al[ksq][1]);
            splitpack(v01.x, v01.y, ah[ksq][2], al[ksq][2]);
            splitpack(v11.x, v11.y, ah[ksq][3], al[ksq][3]);
        }

        for (int nt = wn; nt < NLT; nt += 2) {
            float acc4[4] = {0.f, 0.f, 0.f, 0.f};
            #pragma unroll
            for (int ksq = 0; ksq < NKSC; ksq++) {
                uint2 Bh = g_LEfh[(ksq * NLT + nt) * 32 + lane];
                uint2 Bl = g_LEfl[(ksq * NLT + nt) * 32 + lane];
                mma16816(acc4, ah[ksq], Bh);
                mma16816(acc4, ah[ksq], Bl);
                mma16816(acc4, al[ksq], Bh);
            }
            int col = nt * 8 + (lane & 3) * 2;
            int bA = b0 + ar, bB = bA + 8;
            if (bA < B)
                *(float2*)&out[(size_t)bA * LDIM + col] = make_float2(acc4[0], acc4[1]);
            if (bB < B)
                *(float2*)&out[(size_t)bB * LDIM + col] = make_float2(acc4[2], acc4[3]);
        }
    }
}

// ---------------- launch ----------------
extern "C" void kernel_launch(void* const* d_in, const int* in_sizes, int n_in,
                              void* d_out, int out_size) {
    const float* x  = (const float*)d_in[0];
    const float* v  = (const float*)d_in[1];
    const float* W1 = (const float*)d_in[2];
    const float* b1 = (const float*)d_in[3];
    const float* W2 = (const float*)d_in[4];
    const float* W3 = (const float*)d_in[5];
    const float* b3 = (const float*)d_in[6];
    const float* W4 = (const float*)d_in[7];
    const float* W5 = (const float*)d_in[8];
    const float* b5 = (const float*)d_in[9];
    const float* W6 = (const float*)d_in[10];
    const float* b6 = (const float*)d_in[11];
    const float* W7 = (const float*)d_in[12];
    const float* b7 = (const float*)d_in[13];
    const float* W8 = (const float*)d_in[14];
    const float* b8 = (const float*)d_in[15];
    const float* LE = (const float*)d_in[16];
    float* out = (float*)d_out;

    int B = in_sizes[0] / (NDIM * EDIM);

    k_pairs<<<(KPAD + 255) / 256, 256>>>();
    k_bfrag<<<(NKSTEP * 512 + 255) / 256, 256>>>(v, W7);
    k_lef<<<(NKSC * NLT * 32 + 255) / 256, 256>>>(LE);
    k_prep<<<(3 * EDIM * EDIM + 2 * EDIM + 2 + KC * 128 + 255) / 256, 256>>>(
        W1, b1, W2, W3, b3, W4, W5, W6, W8);
    k_attn4<<<(B + 1) / 2, 256>>>(x, b5, b6, B);

    cudaFuncSetAttribute(k_B, cudaFuncAttributeMaxDynamicSharedMemorySize, SB_SMEM);
    dim3 bgrid((B + 127) / 128, KSPLIT);
    k_B<<<bgrid, 256, SB_SMEM>>>(B);

    cudaFuncSetAttribute(k_C, cudaFuncAttributeMaxDynamicSharedMemorySize, C_SMEM_BYTES);
    k_C<<<(B + TMC - 1) / TMC, 256, C_SMEM_BYTES>>>(b7, b8, out, B);
}

// round 9
// speedup vs baseline: 2.8938x; 1.0050x over previous
#include <cuda_runtime.h>
#include <cuda_bf16.h>
#include <cstdint>

#define EDIM 100
#define NDIM 50
#define TDIM 8
#define CDIM 4
#define UDIM 100
#define LDIM 1000
#define NPAIR 4950
#define KPAD  5120
#define NP    128
#define KSPLIT 2
#define KSLICE (KPAD / KSPLIT)        // 2560
#define NKSTEP (KPAD / 16)            // 320
#define NKS_SL (KSLICE / 16)          // 160
#define NCHUNK (NKS_SL / 4)           // 40
#define MAXB  8192
#define TMC   64
#define KF    208                     // padded 2E for folded GEMM
#define NKSF  13                      // 208/16 ksteps
#define NLT   125                     // 1000/8 label n-tiles

// ---------------- device scratch ----------------
__device__ __align__(16) int2  g_pairs[KPAD];
__device__ float g_h5[MAXB * EDIM];
__device__ float g_h7p[KSPLIT * MAXB * NP];
__device__ __align__(16) float g_u[2 * EDIM];
__device__ float g_z0[2];
__device__ float g_W5t[2 * EDIM * EDIM];
// folded label-path matrices
__device__ float g_Q1[2 * EDIM * LDIM];   // [200][1000] = W8^T @ LE
__device__ float g_P1[EDIM * LDIM];       // [100][1000] = W6^T @ Q1a
__device__ float g_c[LDIM];
// W7 B fragments (k_B), exact mma.sync lane layout
__device__ __align__(16) uint2 g_Bfh[NKSTEP * 16 * 32];
__device__ __align__(16) uint2 g_Bfl[NKSTEP * 16 * 32];
// folded P fragments (k_C2): [ks(13)][nt(125)][lane(32)]
__device__ __align__(16) uint2 g_Pfh[NKSF * NLT * 32];
__device__ __align__(16) uint2 g_Pfl[NKSF * NLT * 32];

// ---------------- helpers ----------------
__device__ __forceinline__ void mma16816(float* d, const uint32_t* a, uint2 b) {
    asm volatile(
        "mma.sync.aligned.m16n8k16.row.col.f32.bf16.bf16.f32 "
        "{%0,%1,%2,%3}, {%4,%5,%6,%7}, {%8,%9}, {%0,%1,%2,%3};"
        : "+f"(d[0]), "+f"(d[1]), "+f"(d[2]), "+f"(d[3])
        : "r"(a[0]), "r"(a[1]), "r"(a[2]), "r"(a[3]), "r"(b.x), "r"(b.y));
}
__device__ __forceinline__ void mkfrag(const float* rw, int2 p0, int2 p1,
                                       uint32_t& hi, uint32_t& lo) {
    float v0 = rw[p0.x] * rw[p0.y];
    float v1 = rw[p1.x] * rw[p1.y];
    __nv_bfloat16 h0 = __float2bfloat16(v0), h1 = __float2bfloat16(v1);
    __nv_bfloat16 l0 = __float2bfloat16(v0 - __bfloat162float(h0));
    __nv_bfloat16 l1 = __float2bfloat16(v1 - __bfloat162float(h1));
    hi = (uint32_t)__bfloat16_as_ushort(h0) | ((uint32_t)__bfloat16_as_ushort(h1) << 16);
    lo = (uint32_t)__bfloat16_as_ushort(l0) | ((uint32_t)__bfloat16_as_ushort(l1) << 16);
}
__device__ __forceinline__ void splitpack(float v0, float v1,
                                          uint32_t& hi, uint32_t& lo) {
    __nv_bfloat16 h0 = __float2bfloat16(v0), h1 = __float2bfloat16(v1);
    __nv_bfloat16 l0 = __float2bfloat16(v0 - __bfloat162float(h0));
    __nv_bfloat16 l1 = __float2bfloat16(v1 - __bfloat162float(h1));
    hi = (uint32_t)__bfloat16_as_ushort(h0) | ((uint32_t)__bfloat16_as_ushort(h1) << 16);
    lo = (uint32_t)__bfloat16_as_ushort(l0) | ((uint32_t)__bfloat16_as_ushort(l1) << 16);
}

// ---------------- pair table ----------------
__global__ void k_pairs() {
    int p = blockIdx.x * blockDim.x + threadIdx.x;
    if (p >= KPAD) return;
    int i = 0, j = 0;
    if (p < NPAIR) {
        int rem = p;
        while (rem >= EDIM - 1 - i) { rem -= EDIM - 1 - i; i++; }
        j = i + 1 + rem;
    }
    g_pairs[p] = make_int2(i, j);
}

// ---------------- build W7 B-fragments (folded vv, hi/lo split) ------------
__global__ void k_bfrag(const float* __restrict__ v, const float* __restrict__ W7) {
    int idx = blockIdx.x * blockDim.x + threadIdx.x;
    if (idx >= NKSTEP * 512) return;
    int ks = idx >> 9, rem = idx & 511;
    int nt = rem >> 5, l = rem & 31;
    int n = nt * 8 + (l >> 2);
    int c0 = (l & 3) * 2;
    uint32_t hreg[2], lreg[2];
    #pragma unroll
    for (int r = 0; r < 2; r++) {
        uint32_t hp = 0, lp = 0;
        #pragma unroll
        for (int h = 0; h < 2; h++) {
            int k = ks * 16 + r * 8 + c0 + h;
            float w = 0.f;
            if (k < NPAIR && n < EDIM) {
                int2 ij = g_pairs[k];
                float vv = 0.f;
                #pragma unroll
                for (int cc = 0; cc < CDIM; cc++)
                    vv += v[ij.x * CDIM + cc] * v[ij.y * CDIM + cc];
                w = W7[n * NPAIR + k] * vv;
            }
            __nv_bfloat16 hi = __float2bfloat16(w);
            __nv_bfloat16 lo = __float2bfloat16(w - __bfloat162float(hi));
            hp |= (uint32_t)__bfloat16_as_ushort(hi) << (h * 16);
            lp |= (uint32_t)__bfloat16_as_ushort(lo) << (h * 16);
        }
        hreg[r] = hp; lreg[r] = lp;
    }
    g_Bfh[idx] = make_uint2(hreg[0], hreg[1]);
    g_Bfl[idx] = make_uint2(lreg[0], lreg[1]);
}

// ---------------- fold: Q1 = W8^T @ LE  [200][1000] ------------------------
__global__ void k_q1(const float* __restrict__ W8, const float* __restrict__ LE) {
    int idx = blockIdx.x * blockDim.x + threadIdx.x;
    if (idx >= 2 * EDIM * LDIM) return;
    int k = idx / LDIM, l = idx % LDIM;
    float a = 0.f;
    #pragma unroll 4
    for (int u = 0; u < UDIM; u++)
        a += W8[u * 2 * EDIM + k] * LE[u * LDIM + l];
    g_Q1[idx] = a;
}

// ---------------- fold: P1 = W6^T @ Q1a ; c = b6@Q1a + b7@Q1b + b8@LE ------
__global__ void k_p1c(const float* __restrict__ W6, const float* __restrict__ b6,
                      const float* __restrict__ b7, const float* __restrict__ b8,
                      const float* __restrict__ LE) {
    int idx = blockIdx.x * blockDim.x + threadIdx.x;
    if (idx < EDIM * LDIM) {
        int e = idx / LDIM, l = idx % LDIM;
        float a = 0.f;
        #pragma unroll 4
        for (int k = 0; k < EDIM; k++)
            a += W6[k * EDIM + e] * g_Q1[k * LDIM + l];
        g_P1[idx] = a;
    } else if (idx < EDIM * LDIM + LDIM) {
        int l = idx - EDIM * LDIM;
        float a = 0.f;
        for (int k = 0; k < EDIM; k++) {
            a += b6[k] * g_Q1[k * LDIM + l];
            a += b7[k] * g_Q1[(EDIM + k) * LDIM + l];
            a += b8[k] * LE[k * LDIM + l];
        }
        g_c[l] = a;
    }
}

// ---------------- build folded-P fragments ---------------------------------
// Pfull[K][l]: K<100 -> P1[K][l]; 100<=K<200 -> Q1[K][l]; else 0
__global__ void k_pf() {
    int idx = blockIdx.x * blockDim.x + threadIdx.x;
    if (idx >= NKSF * NLT * 32) return;
    int ks = idx / (NLT * 32), rem = idx % (NLT * 32);
    int nt = rem >> 5, l = rem & 31;
    int n = nt * 8 + (l >> 2);
    int c0 = (l & 3) * 2;
    uint32_t hreg[2], lreg[2];
    #pragma unroll
    for (int r = 0; r < 2; r++) {
        uint32_t hp = 0, lp = 0;
        #pragma unroll
        for (int h = 0; h < 2; h++) {
            int k = ks * 16 + r * 8 + c0 + h;
            float w = 0.f;
            if (k < EDIM) w = g_P1[k * LDIM + n];
            else if (k < 2 * EDIM) w = g_Q1[k * LDIM + n];
            __nv_bfloat16 hi = __float2bfloat16(w);
            __nv_bfloat16 lo = __float2bfloat16(w - __bfloat162float(hi));
            hp |= (uint32_t)__bfloat16_as_ushort(hi) << (h * 16);
            lp |= (uint32_t)__bfloat16_as_ushort(lo) << (h * 16);
        }
        hreg[r] = hp; lreg[r] = lp;
    }
    g_Pfh[idx] = make_uint2(hreg[0], hreg[1]);
    g_Pfl[idx] = make_uint2(lreg[0], lreg[1]);
}

// ---------------- prep: fold attn MLP, transpose W5 ------------------------
__global__ void k_prep(const float* __restrict__ W1, const float* __restrict__ b1,
                       const float* __restrict__ W2,
                       const float* __restrict__ W3, const float* __restrict__ b3,
                       const float* __restrict__ W4,
                       const float* __restrict__ W5) {
    int idx = blockIdx.x * blockDim.x + threadIdx.x;
    const int N1 = 2 * EDIM * EDIM;
    const int N2 = N1 + 2 * EDIM;
    const int N3 = N2 + 2;
    if (idx < N1) {
        int k = idx / EDIM, e = idx % EDIM;
        g_W5t[idx] = W5[e * 2 * EDIM + k];
    } else if (idx < N2) {
        int j = idx - N1;
        int pool = j / EDIM, e = j % EDIM;
        const float* Wa = pool ? W3 : W1;
        const float* Wb = pool ? W4 : W2;
        float u = 0.f;
        #pragma unroll
        for (int t = 0; t < TDIM; t++) u += Wb[t] * Wa[t * EDIM + e];
        g_u[j] = u;
    } else if (idx < N3) {
        int pool = idx - N2;
        const float* ba = pool ? b3 : b1;
        const float* Wb = pool ? W4 : W2;
        float z = 0.f;
        #pragma unroll
        for (int t = 0; t < TDIM; t++) z += Wb[t] * ba[t];
        g_z0[pool] = z;
    }
}

// ---------------- attention pools + h5 (single x pass, float4) -------------
__global__ void __launch_bounds__(256) k_attn5(const float* __restrict__ x,
                                               const float* __restrict__ b5, int B) {
    __shared__ float zs[2][2][64];
    __shared__ float qp[2][4][2][EDIM];
    __shared__ float qs[2][2 * EDIM];

    int tid = threadIdx.x;
    int g = tid >> 7, wg_tid = tid & 127;
    int lane = tid & 31;
    int w = tid >> 5;
    int ww = w & 3;
    int b = blockIdx.x * 2 + g;
    bool bv = (b < B);
    const float* xb = x + (size_t)b * NDIM * EDIM;

    float4 u0 = make_float4(0.f, 0.f, 0.f, 0.f), u1 = u0;
    if (lane < 25) {
        u0 = *(const float4*)&g_u[4 * lane];
        u1 = *(const float4*)&g_u[EDIM + 4 * lane];
    }
    float z00 = g_z0[0], z01 = g_z0[1];

    int nrows = (ww < 2) ? 13 : 12;
    float4 xv[13];
    #pragma unroll
    for (int r = 0; r < 13; r++) {
        xv[r] = make_float4(0.f, 0.f, 0.f, 0.f);
        if (r < nrows && bv && lane < 25) {
            int n = ww + r * 4;
            xv[r] = *(const float4*)&xb[n * EDIM + 4 * lane];
        }
    }

    #pragma unroll
    for (int r = 0; r < 13; r++) {
        if (r < nrows) {
            float y0 = xv[r].x * u0.x + xv[r].y * u0.y + xv[r].z * u0.z + xv[r].w * u0.w;
            float y1 = xv[r].x * u1.x + xv[r].y * u1.y + xv[r].z * u1.z + xv[r].w * u1.w;
            #pragma unroll
            for (int off = 16; off; off >>= 1) {
                y0 += __shfl_xor_sync(0xffffffffu, y0, off);
                y1 += __shfl_xor_sync(0xffffffffu, y1, off);
            }
            if (lane == 0) {
                int n = ww + r * 4;
                zs[g][0][n] = expf(y0 + z00);
                zs[g][1][n] = expf(y1 + z01);
            }
        }
    }
    __syncthreads();

    if (w < 4) {
        int gg = w >> 1, pool = w & 1;
        float z1 = zs[gg][pool][lane];
        float z2 = (lane < NDIM - 32) ? zs[gg][pool][32 + lane] : -1e30f;
        float m = fmaxf(z1, z2);
        #pragma unroll
        for (int off = 16; off; off >>= 1)
            m = fmaxf(m, __shfl_xor_sync(0xffffffffu, m, off));
        float e1 = expf(z1 - m);
        float e2 = (lane < NDIM - 32) ? expf(z2 - m) : 0.f;
        float s = e1 + e2;
        #pragma unroll
        for (int off = 16; off; off >>= 1)
            s += __shfl_xor_sync(0xffffffffu, s, off);
        zs[gg][pool][lane] = e1 / s;
        if (lane < NDIM - 32) zs[gg][pool][32 + lane] = e2 / s;
    }
    __syncthreads();

    float4 q0 = make_float4(0.f, 0.f, 0.f, 0.f), q1 = q0;
    #pragma unroll
    for (int r = 0; r < 13; r++) {
        if (r < nrows) {
            int n = ww + r * 4;
            float w0 = zs[g][0][n], w1 = zs[g][1][n];
            q0.x += w0 * xv[r].x; q0.y += w0 * xv[r].y;
            q0.z += w0 * xv[r].z; q0.w += w0 * xv[r].w;
            q1.x += w1 * xv[r].x; q1.y += w1 * xv[r].y;
            q1.z += w1 * xv[r].z; q1.w += w1 * xv[r].w;
        }
    }
    if (lane < 25) {
        *(float4*)&qp[g][ww][0][4 * lane] = q0;
        *(float4*)&qp[g][ww][1][4 * lane] = q1;
    }
    __syncthreads();
    if (wg_tid < EDIM) {
        qs[g][wg_tid] = qp[g][0][0][wg_tid] + qp[g][1][0][wg_tid] +
                        qp[g][2][0][wg_tid] + qp[g][3][0][wg_tid];
        qs[g][EDIM + wg_tid] = qp[g][0][1][wg_tid] + qp[g][1][1][wg_tid] +
                               qp[g][2][1][wg_tid] + qp[g][3][1][wg_tid];
    }
    __syncthreads();

    if (wg_tid < EDIM && bv) {
        float a = b5[wg_tid];
        #pragma unroll 4
        for (int k = 0; k < 2 * EDIM; k++)
            a += g_W5t[k * EDIM + wg_tid] * qs[g][k];
        g_h5[(size_t)b * EDIM + wg_tid] = a;
    }
}

// ---------------- kernel B: split-bf16 mma.sync GEMM (unchanged) -----------
#define SB_H5 0
#define SB_PR 51712
#define SB_BH 72192
#define SB_BL 104960
#define SB_SMEM 137728

__global__ void __launch_bounds__(256, 1) k_B(int B) {
    extern __shared__ __align__(16) char smem[];
    float* h5s = (float*)(smem + SB_H5);
    int2*  ps  = (int2*)(smem + SB_PR);

    int tid = threadIdx.x;
    int lane = tid & 31, warp = tid >> 5;
    int wm = warp >> 1, wn = warp & 1;
    int b0 = blockIdx.x * 128;
    int ks = blockIdx.y;

    for (int li = tid; li < 128 * EDIM; li += 256) {
        int r = li / EDIM, e = li % EDIM;
        int b = b0 + r;
        h5s[r * 101 + e] = (b < B) ? g_h5[(size_t)b * EDIM + e] : 0.f;
    }
    {
        const int4* src = (const int4*)(g_pairs + ks * KSLICE);
        int4* dst = (int4*)ps;
        #pragma unroll
        for (int q = 0; q < 5; q++) dst[tid + q * 256] = src[tid + q * 256];
    }

    float acc[2][8][4];
    #pragma unroll
    for (int mi = 0; mi < 2; mi++)
        #pragma unroll
        for (int nt = 0; nt < 8; nt++)
            #pragma unroll
            for (int q = 0; q < 4; q++) acc[mi][nt][q] = 0.f;

    auto stageB = [&](int ch) {
        int s = ch & 1;
        size_t goff = ((size_t)ks * NKS_SL + ch * 4) * 512;
        const float4* srcH = (const float4*)(g_Bfh + goff);
        const float4* srcL = (const float4*)(g_Bfl + goff);
        float4* dH = (float4*)(smem + SB_BH + s * 16384);
        float4* dL = (float4*)(smem + SB_BL + s * 16384);
        #pragma unroll
        for (int q = 0; q < 4; q++) {
            dH[tid + q * 256] = srcH[tid + q * 256];
            dL[tid + q * 256] = srcL[tid + q * 256];
        }
    };

    stageB(0);
    __syncthreads();

    int c0 = (lane & 3) * 2;
    for (int ch = 0; ch < NCHUNK; ch++) {
        if (ch + 1 < NCHUNK) stageB(ch + 1);
        int s = ch & 1;
        const uint2* bhB = (const uint2*)(smem + SB_BH + s * 16384);
        const uint2* blB = (const uint2*)(smem + SB_BL + s * 16384);
        #pragma unroll
        for (int kl = 0; kl < 4; kl++) {
            int kb = (ch * 4 + kl) * 16;
            int2 pA0 = ps[kb + c0], pA1 = ps[kb + c0 + 1];
            int2 pB0 = ps[kb + c0 + 8], pB1 = ps[kb + c0 + 9];
            uint32_t ahi[2][4], alo[2][4];
            #pragma unroll
            for (int mi = 0; mi < 2; mi++) {
                const float* ra = &h5s[(wm * 32 + mi * 16 + (lane >> 2)) * 101];
                const float* rb = ra + 8 * 101;
                mkfrag(ra, pA0, pA1, ahi[mi][0], alo[mi][0]);
                mkfrag(rb, pA0, pA1, ahi[mi][1], alo[mi][1]);
                mkfrag(ra, pB0, pB1, ahi[mi][2], alo[mi][2]);
                mkfrag(rb, pB0, pB1, ahi[mi][3], alo[mi][3]);
            }
            const uint2* bh = bhB + kl * 512 + lane;
            const uint2* bl = blB + kl * 512 + lane;
            #pragma unroll
            for (int nt = 0; nt < 8; nt++) {
                uint2 Bh = bh[(wn * 8 + nt) * 32];
                uint2 Bl = bl[(wn * 8 + nt) * 32];
                #pragma unroll
                for (int mi = 0; mi < 2; mi++) {
                    mma16816(acc[mi][nt], ahi[mi], Bh);
                    mma16816(acc[mi][nt], ahi[mi], Bl);
                    mma16816(acc[mi][nt], alo[mi], Bh);
                }
            }
        }
        __syncthreads();
    }

    float* base = g_h7p + (size_t)ks * MAXB * NP;
    #pragma unroll
    for (int mi = 0; mi < 2; mi++) {
        int row = wm * 32 + mi * 16 + (lane >> 2);
        int bA = b0 + row, bB = bA + 8;
        #pragma unroll
        for (int nt = 0; nt < 8; nt++) {
            int col = wn * 64 + nt * 8 + (lane & 3) * 2;
            if (bA < B)
                *(float2*)&base[(size_t)bA * NP + col] =
                    make_float2(acc[mi][nt][0], acc[mi][nt][1]);
            if (bB < B)
                *(float2*)&base[(size_t)bB * NP + col] =
                    make_float2(acc[mi][nt][2], acc[mi][nt][3]);
        }
    }
}

// ---------------- kernel C2: out = [h5|h7] @ Pfull + c (single mma GEMM) ---
// smem: A [64][208] fp32 = 53248 B
#define C2_SMEM_BYTES (TMC * KF * 4)

__global__ void __launch_bounds__(256) k_C2(float* __restrict__ out, int B) {
    extern __shared__ float As[];   // [64][208]

    int tid = threadIdx.x;
    int b0  = blockIdx.x * TMC;

    // stage A = [h5 | h7raw(sum of partials) | 0pad]
    for (int li = tid; li < TMC * KF; li += 256) {
        int r = li / KF, k = li % KF;
        int b = b0 + r;
        float val = 0.f;
        if (b < B) {
            if (k < EDIM) {
                val = g_h5[(size_t)b * EDIM + k];
            } else if (k < 2 * EDIM) {
                int e = k - EDIM;
                val = g_h7p[(size_t)b * NP + e] +
                      g_h7p[((size_t)MAXB + b) * NP + e];
            }
        }
        As[li] = val;
    }
    __syncthreads();

    int lane = tid & 31, warp = tid >> 5;
    int wm = warp >> 1, wn = warp & 1;
    int ar = wm * 16 + (lane >> 2);
    int ac = (lane & 3) * 2;

    // A-fragments for all 13 ksteps, built once
    uint32_t ah[NKSF][4], al[NKSF][4];
    #pragma unroll
    for (int ks = 0; ks < NKSF; ks++) {
        float2 v00 = *(const float2*)&As[ar * KF + ks * 16 + ac];
        float2 v10 = *(const float2*)&As[(ar + 8) * KF + ks * 16 + ac];
        float2 v01 = *(const float2*)&As[ar * KF + ks * 16 + ac + 8];
        float2 v11 = *(const float2*)&As[(ar + 8) * KF + ks * 16 + ac + 8];
        splitpack(v00.x, v00.y, ah[ks][0], al[ks][0]);
        splitpack(v10.x, v10.y, ah[ks][1], al[ks][1]);
        splitpack(v01.x, v01.y, ah[ks][2], al[ks][2]);
        splitpack(v11.x, v11.y, ah[ks][3], al[ks][3]);
    }

    int colb = (lane & 3) * 2;
    for (int nt = wn; nt < NLT; nt += 2) {
        int col = nt * 8 + colb;
        float2 cv = *(const float2*)&g_c[col];
        float acc4[4] = {cv.x, cv.y, cv.x, cv.y};
        #pragma unroll
        for (int ks = 0; ks < NKSF; ks++) {
            uint2 Bh = g_Pfh[(ks * NLT + nt) * 32 + lane];
            uint2 Bl = g_Pfl[(ks * NLT + nt) * 32 + lane];
            mma16816(acc4, ah[ks], Bh);
            mma16816(acc4, ah[ks], Bl);
            mma16816(acc4, al[ks], Bh);
        }
        int bA = b0 + ar, bB = bA + 8;
        if (bA < B)
            *(float2*)&out[(size_t)bA * LDIM + col] = make_float2(acc4[0], acc4[1]);
        if (bB < B)
            *(float2*)&out[(size_t)bB * LDIM + col] = make_float2(acc4[2], acc4[3]);
    }
}

// ---------------- launch ----------------
extern "C" void kernel_launch(void* const* d_in, const int* in_sizes, int n_in,
                              void* d_out, int out_size) {
    const float* x  = (const float*)d_in[0];
    const float* v  = (const float*)d_in[1];
    const float* W1 = (const float*)d_in[2];
    const float* b1 = (const float*)d_in[3];
    const float* W2 = (const float*)d_in[4];
    const float* W3 = (const float*)d_in[5];
    const float* b3 = (const float*)d_in[6];
    const float* W4 = (const float*)d_in[7];
    const float* W5 = (const float*)d_in[8];
    const float* b5 = (const float*)d_in[9];
    const float* W6 = (const float*)d_in[10];
    const float* b6 = (const float*)d_in[11];
    const float* W7 = (const float*)d_in[12];
    const float* b7 = (const float*)d_in[13];
    const float* W8 = (const float*)d_in[14];
    const float* b8 = (const float*)d_in[15];
    const float* LE = (const float*)d_in[16];
    float* out = (float*)d_out;

    int B = in_sizes[0] / (NDIM * EDIM);

    k_pairs<<<(KPAD + 255) / 256, 256>>>();
    k_bfrag<<<(NKSTEP * 512 + 255) / 256, 256>>>(v, W7);
    k_q1<<<(2 * EDIM * LDIM + 255) / 256, 256>>>(W8, LE);
    k_p1c<<<(EDIM * LDIM + LDIM + 255) / 256, 256>>>(W6, b6, b7, b8, LE);
    k_pf<<<(NKSF * NLT * 32 + 255) / 256, 256>>>();
    k_prep<<<(2 * EDIM * EDIM + 2 * EDIM + 2 + 255) / 256, 256>>>(
        W1, b1, W2, W3, b3, W4, W5);
    k_attn5<<<(B + 1) / 2, 256>>>(x, b5, B);

    cudaFuncSetAttribute(k_B, cudaFuncAttributeMaxDynamicSharedMemorySize, SB_SMEM);
    dim3 bgrid((B + 127) / 128, KSPLIT);
    k_B<<<bgrid, 256, SB_SMEM>>>(B);

    cudaFuncSetAttribute(k_C2, cudaFuncAttributeMaxDynamicSharedMemorySize, C2_SMEM_BYTES);
    k_C2<<<(B + TMC - 1) / TMC, 256, C2_SMEM_BYTES>>>(out, B);
}